// round 5
// baseline (speedup 1.0000x reference)
#include <cuda_runtime.h>
#include <cuda_fp16.h>
#include <cuda_bf16.h>
#include <cstdint>

// Problem-fixed maxima: N=20000, E=320000, F up to 512
#define MAXN 20000
#define MAXE 320000
#define MAXF 512

// -------- scratch (static device memory; no allocations allowed) --------
__device__ int    g_indeg[MAXN];
__device__ float  g_dis[MAXN];
__device__ int    g_offsets[MAXN + 1];
__device__ int    g_cursor[MAXN];
__device__ int    g_csr_src[MAXE];
__device__ float  g_csr_norm[MAXE];
__device__ float  g_h0[(size_t)MAXN * MAXF];
__device__ __half g_Ahi[(size_t)MAXN * MAXF];
__device__ __half g_Alo[(size_t)MAXN * MAXF];
__device__ __half g_Chi[(size_t)MAXN * MAXF];
__device__ __half g_Clo[(size_t)MAXN * MAXF];
__device__ __half g_Bhi[(size_t)MAXF * MAXF];
__device__ __half g_Blo[(size_t)MAXF * MAXF];

__device__ __forceinline__ uint32_t smem_u32(const void* p) {
    uint32_t a;
    asm("{ .reg .u64 t; cvta.to.shared.u64 t, %1; cvt.u32.u64 %0, t; }" : "=r"(a) : "l"(p));
    return a;
}
__device__ __forceinline__ void ldsm_x4(uint32_t& r0, uint32_t& r1, uint32_t& r2, uint32_t& r3,
                                        uint32_t addr) {
    asm volatile("ldmatrix.sync.aligned.m8n8.x4.shared.b16 {%0,%1,%2,%3}, [%4];"
                 : "=r"(r0), "=r"(r1), "=r"(r2), "=r"(r3) : "r"(addr));
}
__device__ __forceinline__ void ldsm_x2(uint32_t& r0, uint32_t& r1, uint32_t addr) {
    asm volatile("ldmatrix.sync.aligned.m8n8.x2.shared.b16 {%0,%1}, [%2];"
                 : "=r"(r0), "=r"(r1) : "r"(addr));
}
__device__ __forceinline__ void mma16816(float* c, uint32_t a0, uint32_t a1, uint32_t a2,
                                         uint32_t a3, uint32_t b0, uint32_t b1) {
    asm volatile(
        "mma.sync.aligned.m16n8k16.row.col.f32.f16.f16.f32 "
        "{%0,%1,%2,%3}, {%4,%5,%6,%7}, {%8,%9}, {%0,%1,%2,%3};"
        : "+f"(c[0]), "+f"(c[1]), "+f"(c[2]), "+f"(c[3])
        : "r"(a0), "r"(a1), "r"(a2), "r"(a3), "r"(b0), "r"(b1));
}
__device__ __forceinline__ void cp16(uint32_t saddr, const void* g, bool v) {
    asm volatile("cp.async.cg.shared.global [%0], [%1], 16, %2;"
                 :: "r"(saddr), "l"(g), "r"(v ? 16 : 0) : "memory");
}
__device__ __forceinline__ void cp_commit() {
    asm volatile("cp.async.commit_group;" ::: "memory");
}
template <int NN>
__device__ __forceinline__ void cp_wait() {
    asm volatile("cp.async.wait_group %0;" :: "n"(NN) : "memory");
}
__device__ __forceinline__ __half2 split_hi2(float a, float b, __half2& lo2) {
    __half ha = __float2half_rn(a), hb = __float2half_rn(b);
    lo2 = __halves2half2(__float2half_rn(a - __half2float(ha)),
                         __float2half_rn(b - __half2float(hb)));
    return __halves2half2(ha, hb);
}

// ---------------- preprocessing ----------------
__global__ void zero_indeg_kernel(int n) {
    int i = blockIdx.x * blockDim.x + threadIdx.x;
    if (i < n) g_indeg[i] = 0;
}
__global__ void count_indeg_kernel(const int* __restrict__ dst, int e) {
    int i = blockIdx.x * blockDim.x + threadIdx.x;
    if (i < e) atomicAdd(&g_indeg[dst[i]], 1);
}
__global__ void compute_dis_kernel(int n) {
    int i = blockIdx.x * blockDim.x + threadIdx.x;
    if (i < n) g_dis[i] = rsqrtf((float)(g_indeg[i] + 1));  // +1 self-loop
}

// spill-free two-pass scan: 1 block, 1024 threads
__global__ void scan_fast_kernel(int n) {
    const int tid = threadIdx.x;
    const int CH = (n + 1023) >> 10;
    const int base = tid * CH;
    int s = 0;
    for (int j = 0; j < CH; j++) {
        int i = base + j;
        if (i < n) s += g_indeg[i];
    }
    const int lane = tid & 31, w = tid >> 5;
    int inc = s;
    #pragma unroll
    for (int o = 1; o < 32; o <<= 1) { int t = __shfl_up_sync(~0u, inc, o); if (lane >= o) inc += t; }
    __shared__ int wsum[32];
    if (lane == 31) wsum[w] = inc;
    __syncthreads();
    if (w == 0) {
        int v = wsum[lane];
        int p = v;
        #pragma unroll
        for (int o = 1; o < 32; o <<= 1) { int t = __shfl_up_sync(~0u, p, o); if (lane >= o) p += t; }
        wsum[lane] = p - v;
    }
    __syncthreads();
    int run = wsum[w] + (inc - s);
    for (int j = 0; j < CH; j++) {
        int i = base + j;
        if (i < n) {
            int v = g_indeg[i];
            g_offsets[i] = run;
            g_cursor[i]  = run;
            run += v;
        }
    }
    if (tid == 1023) g_offsets[n] = run;
}

__global__ void fill_csr_kernel(const int* __restrict__ src, const int* __restrict__ dst, int e) {
    int i = blockIdx.x * blockDim.x + threadIdx.x;
    if (i < e) {
        int s = src[i], d = dst[i];
        int pos = atomicAdd(&g_cursor[d], 1);
        g_csr_src[pos]  = s;
        g_csr_norm[pos] = g_dis[s] * g_dis[d];
    }
}

// -------- W [K,N] row-major -> Bt [N,K] fp16 hi/lo split --------
__global__ void wsplit_kernel(const float* __restrict__ W, __half* __restrict__ hi,
                              __half* __restrict__ lo, int K, int N) {
    int i = blockIdx.x * blockDim.x + threadIdx.x;
    if (i < K * N) {
        int nn = i / K, kk = i % K;
        float f = W[(size_t)kk * N + nn];
        __half h = __float2half_rn(f);
        hi[i] = h;
        lo[i] = __float2half_rn(f - __half2float(h));
    }
}

// ============ HMMA fp16-split GEMM, cp.async double-buffered ============
// C[M,N] = A[M,K] @ Bt[N,K]^T ; 128x128 tile, BK=32, 256 threads, 2 stages.
#define BM 128
#define BN 128
#define BK 32
#define ASTR 40                      // halves per row (padded): 80 bytes
#define TILE_B 10240                 // 128*80 bytes per tile
#define STAGE_B (4 * TILE_B)         // AH AL BH BL
#define GEMM_SMEM (2 * STAGE_B)      // 81920 bytes

template <int EPI>
__global__ void __launch_bounds__(256, 2)
gemm_hmma_kernel(const __half* __restrict__ Ahi, const __half* __restrict__ Alo,
                 const __half* __restrict__ Bhi, const __half* __restrict__ Blo,
                 float* __restrict__ Cf, __half* __restrict__ Chi, __half* __restrict__ Clo,
                 const float* __restrict__ bias, int M, int N, int K) {
    extern __shared__ char smem[];
    const uint32_t sb = smem_u32(smem);

    const int tid = threadIdx.x;
    const int lane = tid & 31, wid = tid >> 5;
    const int wm = wid & 1;
    const int wn = wid >> 1;
    const int by = blockIdx.y;
    const int n0 = blockIdx.x * BN;

    float acc[4][4][4];
    #pragma unroll
    for (int mt = 0; mt < 4; mt++)
        #pragma unroll
        for (int nt = 0; nt < 4; nt++)
            #pragma unroll
            for (int r = 0; r < 4; r++) acc[mt][nt][r] = 0.f;

    const int a_msel = lane >> 3;
    const int a_rowin = (lane & 7) + ((a_msel & 1) << 3);
    const int a_colin = (a_msel >> 1) << 3;
    const int b_rowin = lane & 7;
    const int b_colin = ((lane >> 3) & 1) << 3;

    const int ldrow = tid >> 2;          // 0..63
    const int ldsegB = (tid & 3) * 16;   // byte offset within row
    const int ldsegH = (tid & 3) * 8;    // half offset within row

    // issue one stage's loads
    auto load_stage = [&](int stage, int k0) {
        const uint32_t st = sb + stage * STAGE_B;
        #pragma unroll
        for (int h = 0; h < 2; h++) {
            const int row = ldrow + h * 64;
            const int ar = by * BM + row;
            const bool va = (ar < M);
            const int arc = va ? ar : 0;
            const uint32_t so = row * 80 + ldsegB;
            size_t ai = (size_t)arc * K + k0 + ldsegH;
            cp16(st + so,              Ahi + ai, va);
            cp16(st + TILE_B + so,     Alo + ai, va);
            size_t bi = (size_t)(n0 + row) * K + k0 + ldsegH;
            cp16(st + 2 * TILE_B + so, Bhi + bi, true);
            cp16(st + 3 * TILE_B + so, Blo + bi, true);
        }
        cp_commit();
    };

    const int nc = K / BK;
    load_stage(0, 0);

    for (int c = 0; c < nc; c++) {
        if (c + 1 < nc) {
            load_stage((c + 1) & 1, (c + 1) * BK);
            cp_wait<1>();
        } else {
            cp_wait<0>();
        }
        __syncthreads();

        const uint32_t st = sb + (c & 1) * STAGE_B;
        const uint32_t aAh = st;
        const uint32_t aAl = st + TILE_B;
        const uint32_t aBh = st + 2 * TILE_B;
        const uint32_t aBl = st + 3 * TILE_B;

        #pragma unroll
        for (int ks = 0; ks < 2; ks++) {
            uint32_t bh[4][2], bl[4][2];
            #pragma unroll
            for (int nt = 0; nt < 4; nt++) {
                uint32_t boff = ((wn * 32 + nt * 8 + b_rowin) * ASTR + ks * 16 + b_colin) * 2;
                ldsm_x2(bh[nt][0], bh[nt][1], aBh + boff);
                ldsm_x2(bl[nt][0], bl[nt][1], aBl + boff);
            }
            #pragma unroll
            for (int mt = 0; mt < 4; mt++) {
                uint32_t aoff = ((wm * 64 + mt * 16 + a_rowin) * ASTR + ks * 16 + a_colin) * 2;
                uint32_t ah0, ah1, ah2, ah3, al0, al1, al2, al3;
                ldsm_x4(ah0, ah1, ah2, ah3, aAh + aoff);
                ldsm_x4(al0, al1, al2, al3, aAl + aoff);
                #pragma unroll
                for (int nt = 0; nt < 4; nt++) {
                    mma16816(acc[mt][nt], ah0, ah1, ah2, ah3, bh[nt][0], bh[nt][1]);
                    mma16816(acc[mt][nt], ah0, ah1, ah2, ah3, bl[nt][0], bl[nt][1]);
                    mma16816(acc[mt][nt], al0, al1, al2, al3, bh[nt][0], bh[nt][1]);
                }
            }
        }
        __syncthreads();
    }

    // ---- epilogue ----
    const int erow = lane >> 2;
    const int ecol = (lane & 3) << 1;
    #pragma unroll
    for (int mt = 0; mt < 4; mt++) {
        #pragma unroll
        for (int nt = 0; nt < 4; nt++) {
            const int gc = n0 + wn * 32 + nt * 8 + ecol;
            #pragma unroll
            for (int half = 0; half < 2; half++) {
                const int gr = by * BM + wm * 64 + mt * 16 + erow + half * 8;
                if (gr < M) {
                    float v0 = acc[mt][nt][half * 2 + 0];
                    float v1 = acc[mt][nt][half * 2 + 1];
                    if (EPI == 1) {
                        v0 += bias[gc];     v1 += bias[gc + 1];
                        v0 = (v0 > 0.f) ? v0 : 0.15f * v0;
                        v1 = (v1 > 0.f) ? v1 : 0.15f * v1;
                        __half2 lo2;
                        __half2 hi2 = split_hi2(v0, v1, lo2);
                        size_t o = (size_t)gr * N + gc;
                        *(__half2*)(Chi + o) = hi2;
                        *(__half2*)(Clo + o) = lo2;
                    } else {
                        *(float2*)(Cf + (size_t)gr * N + gc) = make_float2(v0, v1);
                    }
                }
            }
        }
    }
}

// ------- aggregation (warp per node, float4, unroll-2) -------
template <int F, int OUT_SPLIT, int BIASACT>
__global__ void __launch_bounds__(256)
agg_warp_kernel(const float* __restrict__ h, float* __restrict__ outf,
                __half* __restrict__ ohi, __half* __restrict__ olo,
                const float* __restrict__ bias, int n) {
    const int gw = (blockIdx.x * blockDim.x + threadIdx.x) >> 5;
    const int lane = threadIdx.x & 31;
    if (gw >= n) return;
    constexpr int V = F / 128;

    float4 acc[V];
    const float di = g_dis[gw];
    const float selfw = di * di;
    const float4* hrow = (const float4*)(h + (size_t)gw * F);
    #pragma unroll
    for (int v = 0; v < V; v++) {
        float4 t = __ldg(&hrow[lane + 32 * v]);
        acc[v] = make_float4(selfw * t.x, selfw * t.y, selfw * t.z, selfw * t.w);
    }

    const int beg = g_offsets[gw];
    const int end = g_offsets[gw + 1];
    int j = beg;
    for (; j + 1 < end; j += 2) {
        const int   s0 = g_csr_src[j],     s1 = g_csr_src[j + 1];
        const float w0 = g_csr_norm[j],    w1 = g_csr_norm[j + 1];
        const float4* p0 = (const float4*)(h + (size_t)s0 * F);
        const float4* p1 = (const float4*)(h + (size_t)s1 * F);
        #pragma unroll
        for (int v = 0; v < V; v++) {
            float4 t0 = __ldg(&p0[lane + 32 * v]);
            float4 t1 = __ldg(&p1[lane + 32 * v]);
            acc[v].x += w0 * t0.x + w1 * t1.x;
            acc[v].y += w0 * t0.y + w1 * t1.y;
            acc[v].z += w0 * t0.z + w1 * t1.z;
            acc[v].w += w0 * t0.w + w1 * t1.w;
        }
    }
    if (j < end) {
        const int   s = g_csr_src[j];
        const float w = g_csr_norm[j];
        const float4* hs = (const float4*)(h + (size_t)s * F);
        #pragma unroll
        for (int v = 0; v < V; v++) {
            float4 t = __ldg(&hs[lane + 32 * v]);
            acc[v].x += w * t.x; acc[v].y += w * t.y;
            acc[v].z += w * t.z; acc[v].w += w * t.w;
        }
    }

    #pragma unroll
    for (int v = 0; v < V; v++) {
        float4 r = acc[v];
        if (BIASACT) {
            const float4 b = ((const float4*)bias)[lane + 32 * v];
            r.x += b.x; r.y += b.y; r.z += b.z; r.w += b.w;
            r.x = (r.x > 0.f) ? r.x : 0.15f * r.x;
            r.y = (r.y > 0.f) ? r.y : 0.15f * r.y;
            r.z = (r.z > 0.f) ? r.z : 0.15f * r.z;
            r.w = (r.w > 0.f) ? r.w : 0.15f * r.w;
        }
        const size_t o = (size_t)gw * F + (lane + 32 * v) * 4;
        if (OUT_SPLIT) {
            __half2 lo0, lo1;
            __half2 hi0 = split_hi2(r.x, r.y, lo0);
            __half2 hi1 = split_hi2(r.z, r.w, lo1);
            *(__half2*)(ohi + o)     = hi0;
            *(__half2*)(ohi + o + 2) = hi1;
            *(__half2*)(olo + o)     = lo0;
            *(__half2*)(olo + o + 2) = lo1;
        } else {
            *(float4*)(outf + o) = r;
        }
    }
}

// ---- layer-3 aggregation fused with head: agg(128) +b3+lrelu -> 16 -> lrelu(32) -> 2 ----
__global__ void __launch_bounds__(256)
agg_head_kernel(const float* __restrict__ h, const float* __restrict__ b3,
                const float* __restrict__ Wp,  const float* __restrict__ bp,
                const float* __restrict__ Wf1, const float* __restrict__ bf1,
                const float* __restrict__ Wf2, const float* __restrict__ bf2,
                float* __restrict__ out, int n) {
    __shared__ float sWp[128 * 16];
    __shared__ float sWf1[16 * 32];
    __shared__ float sWf2[32 * 2];
    __shared__ float sbp[16], sbf1[32], sbf2[2];

    for (int i = threadIdx.x; i < 128 * 16; i += 256) sWp[i] = Wp[i];
    for (int i = threadIdx.x; i < 16 * 32;  i += 256) sWf1[i] = Wf1[i];
    if (threadIdx.x < 64) sWf2[threadIdx.x] = Wf2[threadIdx.x];
    if (threadIdx.x < 16) sbp[threadIdx.x]  = bp[threadIdx.x];
    if (threadIdx.x < 32) sbf1[threadIdx.x] = bf1[threadIdx.x];
    if (threadIdx.x < 2)  sbf2[threadIdx.x] = bf2[threadIdx.x];
    __syncthreads();

    const int gw = blockIdx.x * 8 + (threadIdx.x >> 5);
    const int lane = threadIdx.x & 31;
    if (gw >= n) return;

    // ---- aggregation (F=128; lane owns cols 4*lane..4*lane+3) ----
    float4 r;
    {
        const float di = g_dis[gw];
        const float selfw = di * di;
        float4 t = __ldg(&((const float4*)(h + (size_t)gw * 128))[lane]);
        r = make_float4(selfw * t.x, selfw * t.y, selfw * t.z, selfw * t.w);
        const int beg = g_offsets[gw];
        const int end = g_offsets[gw + 1];
        int j = beg;
        for (; j + 1 < end; j += 2) {
            const int   s0 = g_csr_src[j],  s1 = g_csr_src[j + 1];
            const float w0 = g_csr_norm[j], w1 = g_csr_norm[j + 1];
            float4 t0 = __ldg(&((const float4*)(h + (size_t)s0 * 128))[lane]);
            float4 t1 = __ldg(&((const float4*)(h + (size_t)s1 * 128))[lane]);
            r.x += w0 * t0.x + w1 * t1.x;
            r.y += w0 * t0.y + w1 * t1.y;
            r.z += w0 * t0.z + w1 * t1.z;
            r.w += w0 * t0.w + w1 * t1.w;
        }
        if (j < end) {
            const int   s = g_csr_src[j];
            const float w = g_csr_norm[j];
            float4 t = __ldg(&((const float4*)(h + (size_t)s * 128))[lane]);
            r.x += w * t.x; r.y += w * t.y; r.z += w * t.z; r.w += w * t.w;
        }
        const float4 b = ((const float4*)b3)[lane];
        r.x += b.x; r.y += b.y; r.z += b.z; r.w += b.w;
        r.x = (r.x > 0.f) ? r.x : 0.15f * r.x;
        r.y = (r.y > 0.f) ? r.y : 0.15f * r.y;
        r.z = (r.z > 0.f) ? r.z : 0.15f * r.z;
        r.w = (r.w > 0.f) ? r.w : 0.15f * r.w;
    }

    // ---- head MLP ----
    const int c0 = lane * 4;
    float s16[16];
    #pragma unroll
    for (int jj = 0; jj < 16; jj++) {
        float p = r.x * sWp[(c0 + 0) * 16 + jj] + r.y * sWp[(c0 + 1) * 16 + jj]
                + r.z * sWp[(c0 + 2) * 16 + jj] + r.w * sWp[(c0 + 3) * 16 + jj];
        #pragma unroll
        for (int o = 16; o > 0; o >>= 1) p += __shfl_xor_sync(0xffffffffu, p, o);
        s16[jj] = p + sbp[jj];
    }

    float tv = sbf1[lane];
    #pragma unroll
    for (int k = 0; k < 16; k++) tv += s16[k] * sWf1[k * 32 + lane];
    tv = (tv > 0.f) ? tv : 0.15f * tv;

    float v0 = tv * sWf2[lane * 2 + 0];
    float v1 = tv * sWf2[lane * 2 + 1];
    #pragma unroll
    for (int o = 16; o > 0; o >>= 1) {
        v0 += __shfl_xor_sync(0xffffffffu, v0, o);
        v1 += __shfl_xor_sync(0xffffffffu, v1, o);
    }
    if (lane == 0) {
        out[(size_t)gw * 2 + 0] = v0 + sbf2[0];
        out[(size_t)gw * 2 + 1] = v1 + sbf2[1];
    }
}

// ---------------- launch ----------------
extern "C" void kernel_launch(void* const* d_in, const int* in_sizes, int n_in,
                              void* d_out, int out_size) {
    const float* x   = (const float*)d_in[0];
    const int*   ei  = (const int*)  d_in[1];
    const float* W1  = (const float*)d_in[3];
    const float* b1  = (const float*)d_in[4];
    const float* W2  = (const float*)d_in[5];
    const float* b2  = (const float*)d_in[6];
    const float* W3  = (const float*)d_in[7];
    const float* b3  = (const float*)d_in[8];
    const float* Wp  = (const float*)d_in[9];
    const float* bp  = (const float*)d_in[10];
    const float* Wf1 = (const float*)d_in[11];
    const float* bf1 = (const float*)d_in[12];
    const float* Wf2 = (const float*)d_in[13];
    const float* bf2 = (const float*)d_in[14];
    float* out = (float*)d_out;

    const int N = in_sizes[0] / 128;
    const int E = in_sizes[1] / 2;
    const int* src = ei;
    const int* dst = ei + E;

    float *h0;
    __half *ahi, *alo, *chi, *clo, *bhi, *blo;
    cudaGetSymbolAddress((void**)&h0, g_h0);
    cudaGetSymbolAddress((void**)&ahi, g_Ahi);
    cudaGetSymbolAddress((void**)&alo, g_Alo);
    cudaGetSymbolAddress((void**)&chi, g_Chi);
    cudaGetSymbolAddress((void**)&clo, g_Clo);
    cudaGetSymbolAddress((void**)&bhi, g_Bhi);
    cudaGetSymbolAddress((void**)&blo, g_Blo);

    __half *b1hi = bhi,          *b1lo = blo;
    __half *b2hi = bhi + 65536,  *b2lo = blo + 65536;
    __half *b3hi = bhi + 196608, *b3lo = blo + 196608;

    static bool attr_set = false;
    if (!attr_set) {
        cudaFuncSetAttribute(gemm_hmma_kernel<0>,
                             cudaFuncAttributeMaxDynamicSharedMemorySize, GEMM_SMEM);
        cudaFuncSetAttribute(gemm_hmma_kernel<1>,
                             cudaFuncAttributeMaxDynamicSharedMemorySize, GEMM_SMEM);
        attr_set = true;
    }

    const int GM = (N + 127) / 128;
    const int AGG_BLK = (N * 32 + 255) / 256;

    // --- preprocessing + weight splits ---
    zero_indeg_kernel<<<(N + 255) / 256, 256>>>(N);
    wsplit_kernel<<<(128 * 512 + 255) / 256, 256>>>(W1, b1hi, b1lo, 128, 512);
    wsplit_kernel<<<(512 * 256 + 255) / 256, 256>>>(W2, b2hi, b2lo, 512, 256);
    wsplit_kernel<<<(256 * 128 + 255) / 256, 256>>>(W3, b3hi, b3lo, 256, 128);
    count_indeg_kernel<<<(E + 255) / 256, 256>>>(dst, E);
    compute_dis_kernel<<<(N + 255) / 256, 256>>>(N);
    scan_fast_kernel<<<1, 1024>>>(N);
    fill_csr_kernel<<<(E + 255) / 256, 256>>>(src, dst, E);

    // --- layer 1 (aggregate-first): split(agg(x)) -> gemm(+bias+lrelu, split out) ---
    agg_warp_kernel<128, 1, 0><<<AGG_BLK, 256>>>(x, nullptr, ahi, alo, nullptr, N);
    {
        dim3 grid(512 / 128, GM);
        gemm_hmma_kernel<1><<<grid, 256, GEMM_SMEM>>>(ahi, alo, b1hi, b1lo, nullptr,
                                                      chi, clo, b1, N, 512, 128);
    }
    // --- layer 2 (transform-first): gemm -> agg(+bias+lrelu, split out) ---
    {
        dim3 grid(256 / 128, GM);
        gemm_hmma_kernel<0><<<grid, 256, GEMM_SMEM>>>(chi, clo, b2hi, b2lo, h0, nullptr,
                                                      nullptr, nullptr, N, 256, 512);
        agg_warp_kernel<256, 1, 1><<<AGG_BLK, 256>>>(h0, nullptr, ahi, alo, b2, N);
    }
    // --- layer 3: gemm -> fused agg + bias + lrelu + MLP head ---
    {
        dim3 grid(128 / 128, GM);
        gemm_hmma_kernel<0><<<grid, 256, GEMM_SMEM>>>(ahi, alo, b3hi, b3lo, h0, nullptr,
                                                      nullptr, nullptr, N, 128, 256);
        agg_head_kernel<<<(N + 7) / 8, 256>>>(h0, b3, Wp, bp, Wf1, bf1, Wf2, bf2, out, N);
    }
}

// round 6
// speedup vs baseline: 1.4327x; 1.4327x over previous
#include <cuda_runtime.h>
#include <cuda_fp16.h>
#include <cuda_bf16.h>
#include <cstdint>

// Problem-fixed maxima: N=20000, E=320000, F up to 512
#define MAXN 20000
#define MAXE 320000
#define MAXF 512

// -------- scratch (static device memory; no allocations allowed) --------
__device__ int    g_indeg[MAXN];
__device__ float  g_dis[MAXN];
__device__ int    g_offsets[MAXN + 1];
__device__ int    g_cursor[MAXN];
__device__ int    g_csr_src[MAXE];
__device__ float  g_csr_norm[MAXE];
__device__ float  g_h0[(size_t)MAXN * MAXF];
__device__ __half g_Ahi[(size_t)MAXN * MAXF];
__device__ __half g_Alo[(size_t)MAXN * MAXF];
__device__ __half g_Chi[(size_t)MAXN * MAXF];
__device__ __half g_Clo[(size_t)MAXN * MAXF];
__device__ __half g_Bhi[(size_t)MAXF * MAXF];
__device__ __half g_Blo[(size_t)MAXF * MAXF];

__device__ __forceinline__ uint32_t smem_u32(const void* p) {
    uint32_t a;
    asm("{ .reg .u64 t; cvta.to.shared.u64 t, %1; cvt.u32.u64 %0, t; }" : "=r"(a) : "l"(p));
    return a;
}
__device__ __forceinline__ void ldsm_x4(uint32_t& r0, uint32_t& r1, uint32_t& r2, uint32_t& r3,
                                        uint32_t addr) {
    asm volatile("ldmatrix.sync.aligned.m8n8.x4.shared.b16 {%0,%1,%2,%3}, [%4];"
                 : "=r"(r0), "=r"(r1), "=r"(r2), "=r"(r3) : "r"(addr));
}
__device__ __forceinline__ void ldsm_x2(uint32_t& r0, uint32_t& r1, uint32_t addr) {
    asm volatile("ldmatrix.sync.aligned.m8n8.x2.shared.b16 {%0,%1}, [%2];"
                 : "=r"(r0), "=r"(r1) : "r"(addr));
}
__device__ __forceinline__ void mma16816(float* c, uint32_t a0, uint32_t a1, uint32_t a2,
                                         uint32_t a3, uint32_t b0, uint32_t b1) {
    asm volatile(
        "mma.sync.aligned.m16n8k16.row.col.f32.f16.f16.f32 "
        "{%0,%1,%2,%3}, {%4,%5,%6,%7}, {%8,%9}, {%0,%1,%2,%3};"
        : "+f"(c[0]), "+f"(c[1]), "+f"(c[2]), "+f"(c[3])
        : "r"(a0), "r"(a1), "r"(a2), "r"(a3), "r"(b0), "r"(b1));
}
__device__ __forceinline__ __half2 split_hi2(float a, float b, __half2& lo2) {
    __half ha = __float2half_rn(a), hb = __float2half_rn(b);
    lo2 = __halves2half2(__float2half_rn(a - __half2float(ha)),
                         __float2half_rn(b - __half2float(hb)));
    return __halves2half2(ha, hb);
}

// ---------------- preprocessing ----------------
__global__ void zero_indeg_kernel(int n) {
    int i = blockIdx.x * blockDim.x + threadIdx.x;
    if (i < n) g_indeg[i] = 0;
}
__global__ void count_indeg_kernel(const int* __restrict__ dst, int e) {
    int i = blockIdx.x * blockDim.x + threadIdx.x;
    if (i < e) atomicAdd(&g_indeg[dst[i]], 1);
}
__global__ void compute_dis_kernel(int n) {
    int i = blockIdx.x * blockDim.x + threadIdx.x;
    if (i < n) g_dis[i] = rsqrtf((float)(g_indeg[i] + 1));  // +1 self-loop
}

// spill-free two-pass scan: 1 block, 1024 threads
__global__ void scan_fast_kernel(int n) {
    const int tid = threadIdx.x;
    const int CH = (n + 1023) >> 10;
    const int base = tid * CH;
    int s = 0;
    for (int j = 0; j < CH; j++) {
        int i = base + j;
        if (i < n) s += g_indeg[i];
    }
    const int lane = tid & 31, w = tid >> 5;
    int inc = s;
    #pragma unroll
    for (int o = 1; o < 32; o <<= 1) { int t = __shfl_up_sync(~0u, inc, o); if (lane >= o) inc += t; }
    __shared__ int wsum[32];
    if (lane == 31) wsum[w] = inc;
    __syncthreads();
    if (w == 0) {
        int v = wsum[lane];
        int p = v;
        #pragma unroll
        for (int o = 1; o < 32; o <<= 1) { int t = __shfl_up_sync(~0u, p, o); if (lane >= o) p += t; }
        wsum[lane] = p - v;
    }
    __syncthreads();
    int run = wsum[w] + (inc - s);
    for (int j = 0; j < CH; j++) {
        int i = base + j;
        if (i < n) {
            int v = g_indeg[i];
            g_offsets[i] = run;
            g_cursor[i]  = run;
            run += v;
        }
    }
    if (tid == 1023) g_offsets[n] = run;
}

__global__ void fill_csr_kernel(const int* __restrict__ src, const int* __restrict__ dst, int e) {
    int i = blockIdx.x * blockDim.x + threadIdx.x;
    if (i < e) {
        int s = src[i], d = dst[i];
        int pos = atomicAdd(&g_cursor[d], 1);
        g_csr_src[pos]  = s;
        g_csr_norm[pos] = g_dis[s] * g_dis[d];
    }
}

// -------- W [K,N] row-major -> Bt [N,K] fp16 hi/lo split --------
__global__ void wsplit_kernel(const float* __restrict__ W, __half* __restrict__ hi,
                              __half* __restrict__ lo, int K, int N) {
    int i = blockIdx.x * blockDim.x + threadIdx.x;
    if (i < K * N) {
        int nn = i / K, kk = i % K;
        float f = W[(size_t)kk * N + nn];
        __half h = __float2half_rn(f);
        hi[i] = h;
        lo[i] = __float2half_rn(f - __half2float(h));
    }
}

// ============ HMMA fp16-split GEMM: C[M,N] = A[M,K] @ Bt[N,K]^T ============
// 128x128 block tile, BK=32, 256 threads (8 warps, 2m x 4n, 64x32 warp tiles).
// EPI=0: plain fp32 out.  EPI=1: bias+lrelu, split fp16 hi/lo out.
#define BM 128
#define BN 128
#define BK 32
#define APAD 8
#define ASTR (BK + APAD)   // 40 halves per row, conflict-free ldmatrix

template <int EPI>
__global__ void __launch_bounds__(256)
gemm_hmma_kernel(const __half* __restrict__ Ahi, const __half* __restrict__ Alo,
                 const __half* __restrict__ Bhi, const __half* __restrict__ Blo,
                 float* __restrict__ Cf, __half* __restrict__ Chi, __half* __restrict__ Clo,
                 const float* __restrict__ bias, int M, int N, int K) {
    __shared__ __half sAh[BM][ASTR];
    __shared__ __half sAl[BM][ASTR];
    __shared__ __half sBh[BN][ASTR];
    __shared__ __half sBl[BN][ASTR];

    const int tid = threadIdx.x;
    const int lane = tid & 31, wid = tid >> 5;
    const int wm = wid & 1;        // 0..1 (m)
    const int wn = wid >> 1;       // 0..3 (n)
    const int by = blockIdx.y;
    const int n0 = blockIdx.x * BN;

    float acc[4][4][4];
    #pragma unroll
    for (int mt = 0; mt < 4; mt++)
        #pragma unroll
        for (int nt = 0; nt < 4; nt++)
            #pragma unroll
            for (int r = 0; r < 4; r++) acc[mt][nt][r] = 0.f;

    const uint32_t aAh = smem_u32(&sAh[0][0]);
    const uint32_t aAl = smem_u32(&sAl[0][0]);
    const uint32_t aBh = smem_u32(&sBh[0][0]);
    const uint32_t aBl = smem_u32(&sBl[0][0]);
    const int a_msel = lane >> 3;
    const int a_rowin = (lane & 7) + ((a_msel & 1) << 3);
    const int a_colin = (a_msel >> 1) << 3;
    const int b_rowin = lane & 7;
    const int b_colin = ((lane >> 3) & 1) << 3;

    const int ldrow = tid >> 2;        // 0..63
    const int ldseg = (tid & 3) << 3;  // 0,8,16,24 halves

    for (int k0 = 0; k0 < K; k0 += BK) {
        #pragma unroll
        for (int h = 0; h < 2; h++) {
            const int row = ldrow + h * 64;
            const int ar = by * BM + row;
            uint4 vh = make_uint4(0, 0, 0, 0), vl = make_uint4(0, 0, 0, 0);
            if (ar < M) {
                size_t ai = (size_t)ar * K + k0 + ldseg;
                vh = *(const uint4*)(Ahi + ai);
                vl = *(const uint4*)(Alo + ai);
            }
            *(uint4*)(&sAh[row][ldseg]) = vh;
            *(uint4*)(&sAl[row][ldseg]) = vl;
            size_t bi = (size_t)(n0 + row) * K + k0 + ldseg;
            *(uint4*)(&sBh[row][ldseg]) = *(const uint4*)(Bhi + bi);
            *(uint4*)(&sBl[row][ldseg]) = *(const uint4*)(Blo + bi);
        }
        __syncthreads();

        #pragma unroll
        for (int ks = 0; ks < 2; ks++) {
            uint32_t bh[4][2], bl[4][2];
            #pragma unroll
            for (int nt = 0; nt < 4; nt++) {
                uint32_t boff = ((wn * 32 + nt * 8 + b_rowin) * ASTR + ks * 16 + b_colin) * 2;
                ldsm_x2(bh[nt][0], bh[nt][1], aBh + boff);
                ldsm_x2(bl[nt][0], bl[nt][1], aBl + boff);
            }
            #pragma unroll
            for (int mt = 0; mt < 4; mt++) {
                uint32_t aoff = ((wm * 64 + mt * 16 + a_rowin) * ASTR + ks * 16 + a_colin) * 2;
                uint32_t ah0, ah1, ah2, ah3, al0, al1, al2, al3;
                ldsm_x4(ah0, ah1, ah2, ah3, aAh + aoff);
                ldsm_x4(al0, al1, al2, al3, aAl + aoff);
                #pragma unroll
                for (int nt = 0; nt < 4; nt++) {
                    mma16816(acc[mt][nt], ah0, ah1, ah2, ah3, bh[nt][0], bh[nt][1]);
                    mma16816(acc[mt][nt], ah0, ah1, ah2, ah3, bl[nt][0], bl[nt][1]);
                    mma16816(acc[mt][nt], al0, al1, al2, al3, bh[nt][0], bh[nt][1]);
                }
            }
        }
        __syncthreads();
    }

    // ---- epilogue ----
    const int erow = lane >> 2;
    const int ecol = (lane & 3) << 1;
    #pragma unroll
    for (int mt = 0; mt < 4; mt++) {
        #pragma unroll
        for (int nt = 0; nt < 4; nt++) {
            const int gc = n0 + wn * 32 + nt * 8 + ecol;
            #pragma unroll
            for (int half = 0; half < 2; half++) {
                const int gr = by * BM + wm * 64 + mt * 16 + erow + half * 8;
                if (gr < M) {
                    float v0 = acc[mt][nt][half * 2 + 0];
                    float v1 = acc[mt][nt][half * 2 + 1];
                    if (EPI == 1) {
                        v0 += bias[gc];     v1 += bias[gc + 1];
                        v0 = (v0 > 0.f) ? v0 : 0.15f * v0;
                        v1 = (v1 > 0.f) ? v1 : 0.15f * v1;
                        __half2 lo2;
                        __half2 hi2 = split_hi2(v0, v1, lo2);
                        size_t o = (size_t)gr * N + gc;
                        *(__half2*)(Chi + o) = hi2;
                        *(__half2*)(Clo + o) = lo2;
                    } else {
                        *(float2*)(Cf + (size_t)gr * N + gc) = make_float2(v0, v1);
                    }
                }
            }
        }
    }
}

// ------- aggregation (warp per node, float4, unroll-2) -------
template <int F, int OUT_SPLIT, int BIASACT>
__global__ void __launch_bounds__(256)
agg_warp_kernel(const float* __restrict__ h, float* __restrict__ outf,
                __half* __restrict__ ohi, __half* __restrict__ olo,
                const float* __restrict__ bias, int n) {
    const int gw = (blockIdx.x * blockDim.x + threadIdx.x) >> 5;
    const int lane = threadIdx.x & 31;
    if (gw >= n) return;
    constexpr int V = F / 128;

    float4 acc[V];
    const float di = g_dis[gw];
    const float selfw = di * di;
    const float4* hrow = (const float4*)(h + (size_t)gw * F);
    #pragma unroll
    for (int v = 0; v < V; v++) {
        float4 t = __ldg(&hrow[lane + 32 * v]);
        acc[v] = make_float4(selfw * t.x, selfw * t.y, selfw * t.z, selfw * t.w);
    }

    const int beg = g_offsets[gw];
    const int end = g_offsets[gw + 1];
    int j = beg;
    for (; j + 1 < end; j += 2) {
        const int   s0 = g_csr_src[j],     s1 = g_csr_src[j + 1];
        const float w0 = g_csr_norm[j],    w1 = g_csr_norm[j + 1];
        const float4* p0 = (const float4*)(h + (size_t)s0 * F);
        const float4* p1 = (const float4*)(h + (size_t)s1 * F);
        #pragma unroll
        for (int v = 0; v < V; v++) {
            float4 t0 = __ldg(&p0[lane + 32 * v]);
            float4 t1 = __ldg(&p1[lane + 32 * v]);
            acc[v].x += w0 * t0.x + w1 * t1.x;
            acc[v].y += w0 * t0.y + w1 * t1.y;
            acc[v].z += w0 * t0.z + w1 * t1.z;
            acc[v].w += w0 * t0.w + w1 * t1.w;
        }
    }
    if (j < end) {
        const int   s = g_csr_src[j];
        const float w = g_csr_norm[j];
        const float4* hs = (const float4*)(h + (size_t)s * F);
        #pragma unroll
        for (int v = 0; v < V; v++) {
            float4 t = __ldg(&hs[lane + 32 * v]);
            acc[v].x += w * t.x; acc[v].y += w * t.y;
            acc[v].z += w * t.z; acc[v].w += w * t.w;
        }
    }

    #pragma unroll
    for (int v = 0; v < V; v++) {
        float4 r = acc[v];
        if (BIASACT) {
            const float4 b = ((const float4*)bias)[lane + 32 * v];
            r.x += b.x; r.y += b.y; r.z += b.z; r.w += b.w;
            r.x = (r.x > 0.f) ? r.x : 0.15f * r.x;
            r.y = (r.y > 0.f) ? r.y : 0.15f * r.y;
            r.z = (r.z > 0.f) ? r.z : 0.15f * r.z;
            r.w = (r.w > 0.f) ? r.w : 0.15f * r.w;
        }
        const size_t o = (size_t)gw * F + (lane + 32 * v) * 4;
        if (OUT_SPLIT) {
            __half2 lo0, lo1;
            __half2 hi0 = split_hi2(r.x, r.y, lo0);
            __half2 hi1 = split_hi2(r.z, r.w, lo1);
            *(__half2*)(ohi + o)     = hi0;
            *(__half2*)(ohi + o + 2) = hi1;
            *(__half2*)(olo + o)     = lo0;
            *(__half2*)(olo + o + 2) = lo1;
        } else {
            *(float4*)(outf + o) = r;
        }
    }
}

// ---- layer-3 aggregation fused with head: agg(128) +b3+lrelu -> 16 -> lrelu(32) -> 2 ----
__global__ void __launch_bounds__(256)
agg_head_kernel(const float* __restrict__ h, const float* __restrict__ b3,
                const float* __restrict__ Wp,  const float* __restrict__ bp,
                const float* __restrict__ Wf1, const float* __restrict__ bf1,
                const float* __restrict__ Wf2, const float* __restrict__ bf2,
                float* __restrict__ out, int n) {
    __shared__ float sWp[128 * 16];
    __shared__ float sWf1[16 * 32];
    __shared__ float sWf2[32 * 2];
    __shared__ float sbp[16], sbf1[32], sbf2[2];

    for (int i = threadIdx.x; i < 128 * 16; i += 256) sWp[i] = Wp[i];
    for (int i = threadIdx.x; i < 16 * 32;  i += 256) sWf1[i] = Wf1[i];
    if (threadIdx.x < 64) sWf2[threadIdx.x] = Wf2[threadIdx.x];
    if (threadIdx.x < 16) sbp[threadIdx.x]  = bp[threadIdx.x];
    if (threadIdx.x < 32) sbf1[threadIdx.x] = bf1[threadIdx.x];
    if (threadIdx.x < 2)  sbf2[threadIdx.x] = bf2[threadIdx.x];
    __syncthreads();

    const int gw = blockIdx.x * 8 + (threadIdx.x >> 5);
    const int lane = threadIdx.x & 31;
    if (gw >= n) return;

    // ---- aggregation (F=128; lane owns cols 4*lane..4*lane+3) ----
    float4 r;
    {
        const float di = g_dis[gw];
        const float selfw = di * di;
        float4 t = __ldg(&((const float4*)(h + (size_t)gw * 128))[lane]);
        r = make_float4(selfw * t.x, selfw * t.y, selfw * t.z, selfw * t.w);
        const int beg = g_offsets[gw];
        const int end = g_offsets[gw + 1];
        int j = beg;
        for (; j + 1 < end; j += 2) {
            const int   s0 = g_csr_src[j],  s1 = g_csr_src[j + 1];
            const float w0 = g_csr_norm[j], w1 = g_csr_norm[j + 1];
            float4 t0 = __ldg(&((const float4*)(h + (size_t)s0 * 128))[lane]);
            float4 t1 = __ldg(&((const float4*)(h + (size_t)s1 * 128))[lane]);
            r.x += w0 * t0.x + w1 * t1.x;
            r.y += w0 * t0.y + w1 * t1.y;
            r.z += w0 * t0.z + w1 * t1.z;
            r.w += w0 * t0.w + w1 * t1.w;
        }
        if (j < end) {
            const int   s = g_csr_src[j];
            const float w = g_csr_norm[j];
            float4 t = __ldg(&((const float4*)(h + (size_t)s * 128))[lane]);
            r.x += w * t.x; r.y += w * t.y; r.z += w * t.z; r.w += w * t.w;
        }
        const float4 b = ((const float4*)b3)[lane];
        r.x += b.x; r.y += b.y; r.z += b.z; r.w += b.w;
        r.x = (r.x > 0.f) ? r.x : 0.15f * r.x;
        r.y = (r.y > 0.f) ? r.y : 0.15f * r.y;
        r.z = (r.z > 0.f) ? r.z : 0.15f * r.z;
        r.w = (r.w > 0.f) ? r.w : 0.15f * r.w;
    }

    // ---- head MLP ----
    const int c0 = lane * 4;
    float s16[16];
    #pragma unroll
    for (int jj = 0; jj < 16; jj++) {
        float p = r.x * sWp[(c0 + 0) * 16 + jj] + r.y * sWp[(c0 + 1) * 16 + jj]
                + r.z * sWp[(c0 + 2) * 16 + jj] + r.w * sWp[(c0 + 3) * 16 + jj];
        #pragma unroll
        for (int o = 16; o > 0; o >>= 1) p += __shfl_xor_sync(0xffffffffu, p, o);
        s16[jj] = p + sbp[jj];
    }

    float tv = sbf1[lane];
    #pragma unroll
    for (int k = 0; k < 16; k++) tv += s16[k] * sWf1[k * 32 + lane];
    tv = (tv > 0.f) ? tv : 0.15f * tv;

    float v0 = tv * sWf2[lane * 2 + 0];
    float v1 = tv * sWf2[lane * 2 + 1];
    #pragma unroll
    for (int o = 16; o > 0; o >>= 1) {
        v0 += __shfl_xor_sync(0xffffffffu, v0, o);
        v1 += __shfl_xor_sync(0xffffffffu, v1, o);
    }
    if (lane == 0) {
        out[(size_t)gw * 2 + 0] = v0 + sbf2[0];
        out[(size_t)gw * 2 + 1] = v1 + sbf2[1];
    }
}

// ---------------- launch ----------------
extern "C" void kernel_launch(void* const* d_in, const int* in_sizes, int n_in,
                              void* d_out, int out_size) {
    const float* x   = (const float*)d_in[0];
    const int*   ei  = (const int*)  d_in[1];
    const float* W1  = (const float*)d_in[3];
    const float* b1  = (const float*)d_in[4];
    const float* W2  = (const float*)d_in[5];
    const float* b2  = (const float*)d_in[6];
    const float* W3  = (const float*)d_in[7];
    const float* b3  = (const float*)d_in[8];
    const float* Wp  = (const float*)d_in[9];
    const float* bp  = (const float*)d_in[10];
    const float* Wf1 = (const float*)d_in[11];
    const float* bf1 = (const float*)d_in[12];
    const float* Wf2 = (const float*)d_in[13];
    const float* bf2 = (const float*)d_in[14];
    float* out = (float*)d_out;

    const int N = in_sizes[0] / 128;
    const int E = in_sizes[1] / 2;
    const int* src = ei;
    const int* dst = ei + E;

    float *h0;
    __half *ahi, *alo, *chi, *clo, *bhi, *blo;
    cudaGetSymbolAddress((void**)&h0, g_h0);
    cudaGetSymbolAddress((void**)&ahi, g_Ahi);
    cudaGetSymbolAddress((void**)&alo, g_Alo);
    cudaGetSymbolAddress((void**)&chi, g_Chi);
    cudaGetSymbolAddress((void**)&clo, g_Clo);
    cudaGetSymbolAddress((void**)&bhi, g_Bhi);
    cudaGetSymbolAddress((void**)&blo, g_Blo);

    __half *b1hi = bhi,          *b1lo = blo;
    __half *b2hi = bhi + 65536,  *b2lo = blo + 65536;
    __half *b3hi = bhi + 196608, *b3lo = blo + 196608;

    const int GM = (N + 127) / 128;
    const int AGG_BLK = (N * 32 + 255) / 256;

    // --- preprocessing + weight splits ---
    zero_indeg_kernel<<<(N + 255) / 256, 256>>>(N);
    wsplit_kernel<<<(128 * 512 + 255) / 256, 256>>>(W1, b1hi, b1lo, 128, 512);
    wsplit_kernel<<<(512 * 256 + 255) / 256, 256>>>(W2, b2hi, b2lo, 512, 256);
    wsplit_kernel<<<(256 * 128 + 255) / 256, 256>>>(W3, b3hi, b3lo, 256, 128);
    count_indeg_kernel<<<(E + 255) / 256, 256>>>(dst, E);
    compute_dis_kernel<<<(N + 255) / 256, 256>>>(N);
    scan_fast_kernel<<<1, 1024>>>(N);
    fill_csr_kernel<<<(E + 255) / 256, 256>>>(src, dst, E);

    // --- layer 1 (aggregate-first): split(agg(x)) -> gemm(+bias+lrelu, split out) ---
    agg_warp_kernel<128, 1, 0><<<AGG_BLK, 256>>>(x, nullptr, ahi, alo, nullptr, N);
    {
        dim3 grid(512 / 128, GM);
        gemm_hmma_kernel<1><<<grid, 256>>>(ahi, alo, b1hi, b1lo, nullptr,
                                           chi, clo, b1, N, 512, 128);
    }
    // --- layer 2 (transform-first): gemm -> agg(+bias+lrelu, split out) ---
    {
        dim3 grid(256 / 128, GM);
        gemm_hmma_kernel<0><<<grid, 256>>>(chi, clo, b2hi, b2lo, h0, nullptr,
                                           nullptr, nullptr, N, 256, 512);
        agg_warp_kernel<256, 1, 1><<<AGG_BLK, 256>>>(h0, nullptr, ahi, alo, b2, N);
    }
    // --- layer 3: gemm -> fused agg + bias + lrelu + MLP head ---
    {
        dim3 grid(128 / 128, GM);
        gemm_hmma_kernel<0><<<grid, 256>>>(ahi, alo, b3hi, b3lo, h0, nullptr,
                                           nullptr, nullptr, N, 128, 256);
        agg_head_kernel<<<(N + 7) / 8, 256>>>(h0, b3, Wp, bp, Wf1, bf1, Wf2, bf2, out, N);
    }
}

// round 7
// speedup vs baseline: 1.4346x; 1.0013x over previous
#include <cuda_runtime.h>
#include <cuda_fp16.h>
#include <cuda_bf16.h>
#include <cstdint>

// Problem-fixed maxima: N=20000, E=320000, F up to 512
#define MAXN 20000
#define MAXE 320000
#define MAXF 512

// -------- scratch (static device memory; no allocations allowed) --------
__device__ int    g_indeg[MAXN];
__device__ float  g_dis[MAXN];
__device__ int    g_offsets[MAXN + 1];
__device__ int    g_cursor[MAXN];
__device__ int    g_csr_src[MAXE];
__device__ float  g_csr_norm[MAXE];
__device__ float  g_h0[(size_t)MAXN * MAXF];
__device__ __half g_Ahi[(size_t)MAXN * MAXF];
__device__ __half g_Alo[(size_t)MAXN * MAXF];
__device__ __half g_Chi[(size_t)MAXN * MAXF];
__device__ __half g_Clo[(size_t)MAXN * MAXF];
__device__ __half g_Bhi[(size_t)MAXF * MAXF];
__device__ __half g_Blo[(size_t)MAXF * MAXF];

__device__ __forceinline__ uint32_t smem_u32(const void* p) {
    uint32_t a;
    asm("{ .reg .u64 t; cvta.to.shared.u64 t, %1; cvt.u32.u64 %0, t; }" : "=r"(a) : "l"(p));
    return a;
}
__device__ __forceinline__ void ldsm_x4(uint32_t& r0, uint32_t& r1, uint32_t& r2, uint32_t& r3,
                                        uint32_t addr) {
    asm volatile("ldmatrix.sync.aligned.m8n8.x4.shared.b16 {%0,%1,%2,%3}, [%4];"
                 : "=r"(r0), "=r"(r1), "=r"(r2), "=r"(r3) : "r"(addr));
}
__device__ __forceinline__ void ldsm_x2(uint32_t& r0, uint32_t& r1, uint32_t addr) {
    asm volatile("ldmatrix.sync.aligned.m8n8.x2.shared.b16 {%0,%1}, [%2];"
                 : "=r"(r0), "=r"(r1) : "r"(addr));
}
__device__ __forceinline__ void mma16816(float* c, uint32_t a0, uint32_t a1, uint32_t a2,
                                         uint32_t a3, uint32_t b0, uint32_t b1) {
    asm volatile(
        "mma.sync.aligned.m16n8k16.row.col.f32.f16.f16.f32 "
        "{%0,%1,%2,%3}, {%4,%5,%6,%7}, {%8,%9}, {%0,%1,%2,%3};"
        : "+f"(c[0]), "+f"(c[1]), "+f"(c[2]), "+f"(c[3])
        : "r"(a0), "r"(a1), "r"(a2), "r"(a3), "r"(b0), "r"(b1));
}
__device__ __forceinline__ __half2 split_hi2(float a, float b, __half2& lo2) {
    __half ha = __float2half_rn(a), hb = __float2half_rn(b);
    lo2 = __halves2half2(__float2half_rn(a - __half2float(ha)),
                         __float2half_rn(b - __half2float(hb)));
    return __halves2half2(ha, hb);
}

// ---------------- preprocessing ----------------
__global__ void zero_indeg_kernel(int n) {
    int i = blockIdx.x * blockDim.x + threadIdx.x;
    if (i < n) g_indeg[i] = 0;
}
__global__ void count_indeg_kernel(const int* __restrict__ dst, int e) {
    int i = blockIdx.x * blockDim.x + threadIdx.x;
    if (i < e) atomicAdd(&g_indeg[dst[i]], 1);
}
__global__ void compute_dis_kernel(int n) {
    int i = blockIdx.x * blockDim.x + threadIdx.x;
    if (i < n) g_dis[i] = rsqrtf((float)(g_indeg[i] + 1));  // +1 self-loop
}

// spill-free two-pass scan: 1 block, 1024 threads
__global__ void scan_fast_kernel(int n) {
    const int tid = threadIdx.x;
    const int CH = (n + 1023) >> 10;
    const int base = tid * CH;
    int s = 0;
    for (int j = 0; j < CH; j++) {
        int i = base + j;
        if (i < n) s += g_indeg[i];
    }
    const int lane = tid & 31, w = tid >> 5;
    int inc = s;
    #pragma unroll
    for (int o = 1; o < 32; o <<= 1) { int t = __shfl_up_sync(~0u, inc, o); if (lane >= o) inc += t; }
    __shared__ int wsum[32];
    if (lane == 31) wsum[w] = inc;
    __syncthreads();
    if (w == 0) {
        int v = wsum[lane];
        int p = v;
        #pragma unroll
        for (int o = 1; o < 32; o <<= 1) { int t = __shfl_up_sync(~0u, p, o); if (lane >= o) p += t; }
        wsum[lane] = p - v;
    }
    __syncthreads();
    int run = wsum[w] + (inc - s);
    for (int j = 0; j < CH; j++) {
        int i = base + j;
        if (i < n) {
            int v = g_indeg[i];
            g_offsets[i] = run;
            g_cursor[i]  = run;
            run += v;
        }
    }
    if (tid == 1023) g_offsets[n] = run;
}

__global__ void fill_csr_kernel(const int* __restrict__ src, const int* __restrict__ dst, int e) {
    int i = blockIdx.x * blockDim.x + threadIdx.x;
    if (i < e) {
        int s = src[i], d = dst[i];
        int pos = atomicAdd(&g_cursor[d], 1);
        g_csr_src[pos]  = s;
        g_csr_norm[pos] = g_dis[s] * g_dis[d];
    }
}

// -------- W [K,N] row-major -> Bt [N,K] fp16 hi/lo split (tiled transpose) --------
// grid (N/32, K/32), block 256 = 32x8
__global__ void wsplit_t_kernel(const float* __restrict__ W, __half* __restrict__ hi,
                                __half* __restrict__ lo, int K, int N) {
    __shared__ float tile[32][33];
    const int bx = blockIdx.x * 32;   // N origin
    const int by = blockIdx.y * 32;   // K origin
    const int tx = threadIdx.x & 31, ty = threadIdx.x >> 5;
    #pragma unroll
    for (int r = 0; r < 32; r += 8)
        tile[ty + r][tx] = W[(size_t)(by + ty + r) * N + bx + tx];
    __syncthreads();
    #pragma unroll
    for (int r = 0; r < 32; r += 8) {
        float f = tile[tx][ty + r];   // = W[by+tx][bx+ty+r]
        __half h = __float2half_rn(f);
        size_t o = (size_t)(bx + ty + r) * K + by + tx;
        hi[o] = h;
        lo[o] = __float2half_rn(f - __half2float(h));
    }
}

// ============ HMMA fp16-split GEMM, register-prefetch double buffer ============
// C[M,N] = A[M,K] @ Bt[N,K]^T ; 128x128 tile, BK=32, 256 threads.
// EPI=0: plain fp32 out.  EPI=1: bias+lrelu, split fp16 hi/lo out.
#define BM 128
#define BN 128
#define BK 32
#define APAD 8
#define ASTR (BK + APAD)   // 40 halves per row, conflict-free ldmatrix

template <int EPI>
__global__ void __launch_bounds__(256)
gemm_hmma_kernel(const __half* __restrict__ Ahi, const __half* __restrict__ Alo,
                 const __half* __restrict__ Bhi, const __half* __restrict__ Blo,
                 float* __restrict__ Cf, __half* __restrict__ Chi, __half* __restrict__ Clo,
                 const float* __restrict__ bias, int M, int N, int K) {
    __shared__ __half sAh[BM][ASTR];
    __shared__ __half sAl[BM][ASTR];
    __shared__ __half sBh[BN][ASTR];
    __shared__ __half sBl[BN][ASTR];

    const int tid = threadIdx.x;
    const int lane = tid & 31, wid = tid >> 5;
    const int wm = wid & 1;        // 0..1 (m)
    const int wn = wid >> 1;       // 0..3 (n)
    const int by = blockIdx.y;
    const int n0 = blockIdx.x * BN;

    float acc[4][4][4];
    #pragma unroll
    for (int mt = 0; mt < 4; mt++)
        #pragma unroll
        for (int nt = 0; nt < 4; nt++)
            #pragma unroll
            for (int r = 0; r < 4; r++) acc[mt][nt][r] = 0.f;

    const uint32_t aAh = smem_u32(&sAh[0][0]);
    const uint32_t aAl = smem_u32(&sAl[0][0]);
    const uint32_t aBh = smem_u32(&sBh[0][0]);
    const uint32_t aBl = smem_u32(&sBl[0][0]);
    const int a_msel = lane >> 3;
    const int a_rowin = (lane & 7) + ((a_msel & 1) << 3);
    const int a_colin = (a_msel >> 1) << 3;
    const int b_rowin = lane & 7;
    const int b_colin = ((lane >> 3) & 1) << 3;

    const int ldrow = tid >> 2;        // 0..63
    const int ldseg = (tid & 3) << 3;  // 0,8,16,24 halves

    // register prefetch buffers (2 rows per thread, 4 tiles)
    uint4 rAh[2], rAl[2], rBh[2], rBl[2];

    auto fetch = [&](int k0) {
        #pragma unroll
        for (int h = 0; h < 2; h++) {
            const int row = ldrow + h * 64;
            const int ar = by * BM + row;
            if (ar < M) {
                size_t ai = (size_t)ar * K + k0 + ldseg;
                rAh[h] = *(const uint4*)(Ahi + ai);
                rAl[h] = *(const uint4*)(Alo + ai);
            } else {
                rAh[h] = make_uint4(0, 0, 0, 0);
                rAl[h] = make_uint4(0, 0, 0, 0);
            }
            size_t bi = (size_t)(n0 + row) * K + k0 + ldseg;
            rBh[h] = *(const uint4*)(Bhi + bi);
            rBl[h] = *(const uint4*)(Blo + bi);
        }
    };

    const int nc = K / BK;
    fetch(0);

    for (int c = 0; c < nc; c++) {
        // regs -> smem
        #pragma unroll
        for (int h = 0; h < 2; h++) {
            const int row = ldrow + h * 64;
            *(uint4*)(&sAh[row][ldseg]) = rAh[h];
            *(uint4*)(&sAl[row][ldseg]) = rAl[h];
            *(uint4*)(&sBh[row][ldseg]) = rBh[h];
            *(uint4*)(&sBl[row][ldseg]) = rBl[h];
        }
        __syncthreads();

        // prefetch next chunk (LDGs overlap with MMAs below)
        if (c + 1 < nc) fetch((c + 1) * BK);

        #pragma unroll
        for (int ks = 0; ks < 2; ks++) {
            uint32_t bh[4][2], bl[4][2];
            #pragma unroll
            for (int nt = 0; nt < 4; nt++) {
                uint32_t boff = ((wn * 32 + nt * 8 + b_rowin) * ASTR + ks * 16 + b_colin) * 2;
                ldsm_x2(bh[nt][0], bh[nt][1], aBh + boff);
                ldsm_x2(bl[nt][0], bl[nt][1], aBl + boff);
            }
            #pragma unroll
            for (int mt = 0; mt < 4; mt++) {
                uint32_t aoff = ((wm * 64 + mt * 16 + a_rowin) * ASTR + ks * 16 + a_colin) * 2;
                uint32_t ah0, ah1, ah2, ah3, al0, al1, al2, al3;
                ldsm_x4(ah0, ah1, ah2, ah3, aAh + aoff);
                ldsm_x4(al0, al1, al2, al3, aAl + aoff);
                #pragma unroll
                for (int nt = 0; nt < 4; nt++) {
                    mma16816(acc[mt][nt], ah0, ah1, ah2, ah3, bh[nt][0], bh[nt][1]);
                    mma16816(acc[mt][nt], ah0, ah1, ah2, ah3, bl[nt][0], bl[nt][1]);
                    mma16816(acc[mt][nt], al0, al1, al2, al3, bh[nt][0], bh[nt][1]);
                }
            }
        }
        __syncthreads();
    }

    // ---- epilogue ----
    const int erow = lane >> 2;
    const int ecol = (lane & 3) << 1;
    #pragma unroll
    for (int mt = 0; mt < 4; mt++) {
        #pragma unroll
        for (int nt = 0; nt < 4; nt++) {
            const int gc = n0 + wn * 32 + nt * 8 + ecol;
            #pragma unroll
            for (int half = 0; half < 2; half++) {
                const int gr = by * BM + wm * 64 + mt * 16 + erow + half * 8;
                if (gr < M) {
                    float v0 = acc[mt][nt][half * 2 + 0];
                    float v1 = acc[mt][nt][half * 2 + 1];
                    if (EPI == 1) {
                        v0 += bias[gc];     v1 += bias[gc + 1];
                        v0 = (v0 > 0.f) ? v0 : 0.15f * v0;
                        v1 = (v1 > 0.f) ? v1 : 0.15f * v1;
                        __half2 lo2;
                        __half2 hi2 = split_hi2(v0, v1, lo2);
                        size_t o = (size_t)gr * N + gc;
                        *(__half2*)(Chi + o) = hi2;
                        *(__half2*)(Clo + o) = lo2;
                    } else {
                        *(float2*)(Cf + (size_t)gr * N + gc) = make_float2(v0, v1);
                    }
                }
            }
        }
    }
}

// ------- aggregation (warp per node, float4, simple loop) -------
template <int F, int OUT_SPLIT, int BIASACT>
__global__ void __launch_bounds__(256)
agg_warp_kernel(const float* __restrict__ h, float* __restrict__ outf,
                __half* __restrict__ ohi, __half* __restrict__ olo,
                const float* __restrict__ bias, int n) {
    const int gw = (blockIdx.x * blockDim.x + threadIdx.x) >> 5;
    const int lane = threadIdx.x & 31;
    if (gw >= n) return;
    constexpr int V = F / 128;

    float4 acc[V];
    const float di = g_dis[gw];
    const float selfw = di * di;
    const float4* hrow = (const float4*)(h + (size_t)gw * F);
    #pragma unroll
    for (int v = 0; v < V; v++) {
        float4 t = hrow[lane + 32 * v];
        acc[v] = make_float4(selfw * t.x, selfw * t.y, selfw * t.z, selfw * t.w);
    }

    const int beg = g_offsets[gw];
    const int end = g_offsets[gw + 1];
    for (int j = beg; j < end; j++) {
        const int   s = g_csr_src[j];
        const float w = g_csr_norm[j];
        const float4* hs = (const float4*)(h + (size_t)s * F);
        #pragma unroll
        for (int v = 0; v < V; v++) {
            float4 t = hs[lane + 32 * v];
            acc[v].x += w * t.x; acc[v].y += w * t.y;
            acc[v].z += w * t.z; acc[v].w += w * t.w;
        }
    }

    #pragma unroll
    for (int v = 0; v < V; v++) {
        float4 r = acc[v];
        if (BIASACT) {
            const float4 b = ((const float4*)bias)[lane + 32 * v];
            r.x += b.x; r.y += b.y; r.z += b.z; r.w += b.w;
            r.x = (r.x > 0.f) ? r.x : 0.15f * r.x;
            r.y = (r.y > 0.f) ? r.y : 0.15f * r.y;
            r.z = (r.z > 0.f) ? r.z : 0.15f * r.z;
            r.w = (r.w > 0.f) ? r.w : 0.15f * r.w;
        }
        const size_t o = (size_t)gw * F + (lane + 32 * v) * 4;
        if (OUT_SPLIT) {
            __half2 lo0, lo1;
            __half2 hi0 = split_hi2(r.x, r.y, lo0);
            __half2 hi1 = split_hi2(r.z, r.w, lo1);
            *(__half2*)(ohi + o)     = hi0;
            *(__half2*)(ohi + o + 2) = hi1;
            *(__half2*)(olo + o)     = lo0;
            *(__half2*)(olo + o + 2) = lo1;
        } else {
            *(float4*)(outf + o) = r;
        }
    }
}

// ---- layer-3 aggregation fused with head: agg(128) +b3+lrelu -> 16 -> lrelu(32) -> 2 ----
__global__ void __launch_bounds__(256)
agg_head_kernel(const float* __restrict__ h, const float* __restrict__ b3,
                const float* __restrict__ Wp,  const float* __restrict__ bp,
                const float* __restrict__ Wf1, const float* __restrict__ bf1,
                const float* __restrict__ Wf2, const float* __restrict__ bf2,
                float* __restrict__ out, int n) {
    __shared__ float sWp[128 * 16];
    __shared__ float sWf1[16 * 32];
    __shared__ float sWf2[32 * 2];
    __shared__ float sbp[16], sbf1[32], sbf2[2];

    for (int i = threadIdx.x; i < 128 * 16; i += 256) sWp[i] = Wp[i];
    for (int i = threadIdx.x; i < 16 * 32;  i += 256) sWf1[i] = Wf1[i];
    if (threadIdx.x < 64) sWf2[threadIdx.x] = Wf2[threadIdx.x];
    if (threadIdx.x < 16) sbp[threadIdx.x]  = bp[threadIdx.x];
    if (threadIdx.x < 32) sbf1[threadIdx.x] = bf1[threadIdx.x];
    if (threadIdx.x < 2)  sbf2[threadIdx.x] = bf2[threadIdx.x];
    __syncthreads();

    const int gw = blockIdx.x * 8 + (threadIdx.x >> 5);
    const int lane = threadIdx.x & 31;
    if (gw >= n) return;

    // ---- aggregation (F=128; lane owns cols 4*lane..4*lane+3) ----
    float4 r;
    {
        const float di = g_dis[gw];
        const float selfw = di * di;
        float4 t = ((const float4*)(h + (size_t)gw * 128))[lane];
        r = make_float4(selfw * t.x, selfw * t.y, selfw * t.z, selfw * t.w);
        const int beg = g_offsets[gw];
        const int end = g_offsets[gw + 1];
        for (int j = beg; j < end; j++) {
            const int   s = g_csr_src[j];
            const float w = g_csr_norm[j];
            float4 ts = ((const float4*)(h + (size_t)s * 128))[lane];
            r.x += w * ts.x; r.y += w * ts.y; r.z += w * ts.z; r.w += w * ts.w;
        }
        const float4 b = ((const float4*)b3)[lane];
        r.x += b.x; r.y += b.y; r.z += b.z; r.w += b.w;
        r.x = (r.x > 0.f) ? r.x : 0.15f * r.x;
        r.y = (r.y > 0.f) ? r.y : 0.15f * r.y;
        r.z = (r.z > 0.f) ? r.z : 0.15f * r.z;
        r.w = (r.w > 0.f) ? r.w : 0.15f * r.w;
    }

    // ---- head MLP ----
    const int c0 = lane * 4;
    float s16[16];
    #pragma unroll
    for (int jj = 0; jj < 16; jj++) {
        float p = r.x * sWp[(c0 + 0) * 16 + jj] + r.y * sWp[(c0 + 1) * 16 + jj]
                + r.z * sWp[(c0 + 2) * 16 + jj] + r.w * sWp[(c0 + 3) * 16 + jj];
        #pragma unroll
        for (int o = 16; o > 0; o >>= 1) p += __shfl_xor_sync(0xffffffffu, p, o);
        s16[jj] = p + sbp[jj];
    }

    float tv = sbf1[lane];
    #pragma unroll
    for (int k = 0; k < 16; k++) tv += s16[k] * sWf1[k * 32 + lane];
    tv = (tv > 0.f) ? tv : 0.15f * tv;

    float v0 = tv * sWf2[lane * 2 + 0];
    float v1 = tv * sWf2[lane * 2 + 1];
    #pragma unroll
    for (int o = 16; o > 0; o >>= 1) {
        v0 += __shfl_xor_sync(0xffffffffu, v0, o);
        v1 += __shfl_xor_sync(0xffffffffu, v1, o);
    }
    if (lane == 0) {
        out[(size_t)gw * 2 + 0] = v0 + sbf2[0];
        out[(size_t)gw * 2 + 1] = v1 + sbf2[1];
    }
}

// ---------------- launch ----------------
extern "C" void kernel_launch(void* const* d_in, const int* in_sizes, int n_in,
                              void* d_out, int out_size) {
    const float* x   = (const float*)d_in[0];
    const int*   ei  = (const int*)  d_in[1];
    const float* W1  = (const float*)d_in[3];
    const float* b1  = (const float*)d_in[4];
    const float* W2  = (const float*)d_in[5];
    const float* b2  = (const float*)d_in[6];
    const float* W3  = (const float*)d_in[7];
    const float* b3  = (const float*)d_in[8];
    const float* Wp  = (const float*)d_in[9];
    const float* bp  = (const float*)d_in[10];
    const float* Wf1 = (const float*)d_in[11];
    const float* bf1 = (const float*)d_in[12];
    const float* Wf2 = (const float*)d_in[13];
    const float* bf2 = (const float*)d_in[14];
    float* out = (float*)d_out;

    const int N = in_sizes[0] / 128;
    const int E = in_sizes[1] / 2;
    const int* src = ei;
    const int* dst = ei + E;

    float *h0;
    __half *ahi, *alo, *chi, *clo, *bhi, *blo;
    cudaGetSymbolAddress((void**)&h0, g_h0);
    cudaGetSymbolAddress((void**)&ahi, g_Ahi);
    cudaGetSymbolAddress((void**)&alo, g_Alo);
    cudaGetSymbolAddress((void**)&chi, g_Chi);
    cudaGetSymbolAddress((void**)&clo, g_Clo);
    cudaGetSymbolAddress((void**)&bhi, g_Bhi);
    cudaGetSymbolAddress((void**)&blo, g_Blo);

    __half *b1hi = bhi,          *b1lo = blo;            // 128*512
    __half *b2hi = bhi + 65536,  *b2lo = blo + 65536;    // 512*256
    __half *b3hi = bhi + 196608, *b3lo = blo + 196608;   // 256*128

    const int GM = (N + 127) / 128;
    const int AGG_BLK = (N * 32 + 255) / 256;

    // --- preprocessing + weight splits ---
    zero_indeg_kernel<<<(N + 255) / 256, 256>>>(N);
    { dim3 g(512 / 32, 128 / 32); wsplit_t_kernel<<<g, 256>>>(W1, b1hi, b1lo, 128, 512); }
    { dim3 g(256 / 32, 512 / 32); wsplit_t_kernel<<<g, 256>>>(W2, b2hi, b2lo, 512, 256); }
    { dim3 g(128 / 32, 256 / 32); wsplit_t_kernel<<<g, 256>>>(W3, b3hi, b3lo, 256, 128); }
    count_indeg_kernel<<<(E + 255) / 256, 256>>>(dst, E);
    compute_dis_kernel<<<(N + 255) / 256, 256>>>(N);
    scan_fast_kernel<<<1, 1024>>>(N);
    fill_csr_kernel<<<(E + 255) / 256, 256>>>(src, dst, E);

    // --- layer 1 (aggregate-first): split(agg(x)) -> gemm(+bias+lrelu, split out) ---
    agg_warp_kernel<128, 1, 0><<<AGG_BLK, 256>>>(x, nullptr, ahi, alo, nullptr, N);
    {
        dim3 grid(512 / 128, GM);
        gemm_hmma_kernel<1><<<grid, 256>>>(ahi, alo, b1hi, b1lo, nullptr,
                                           chi, clo, b1, N, 512, 128);
    }
    // --- layer 2 (transform-first): gemm -> agg(+bias+lrelu, split out) ---
    {
        dim3 grid(256 / 128, GM);
        gemm_hmma_kernel<0><<<grid, 256>>>(chi, clo, b2hi, b2lo, h0, nullptr,
                                           nullptr, nullptr, N, 256, 512);
        agg_warp_kernel<256, 1, 1><<<AGG_BLK, 256>>>(h0, nullptr, ahi, alo, b2, N);
    }
    // --- layer 3: gemm -> fused agg + bias + lrelu + MLP head ---
    {
        dim3 grid(128 / 128, GM);
        gemm_hmma_kernel<0><<<grid, 256>>>(ahi, alo, b3hi, b3lo, h0, nullptr,
                                           nullptr, nullptr, N, 128, 256);
        agg_head_kernel<<<(N + 7) / 8, 256>>>(h0, b3, Wp, bp, Wf1, bf1, Wf2, bf2, out, N);
    }
}

// round 8
// speedup vs baseline: 1.5310x; 1.0672x over previous
#include <cuda_runtime.h>
#include <cuda_fp16.h>
#include <cuda_bf16.h>
#include <cstdint>

// Problem-fixed maxima: N=20000, E=320000, F up to 512
#define MAXN 20000
#define MAXE 320000
#define MAXF 512

// -------- scratch (static device memory; no allocations allowed) --------
__device__ int    g_indeg[MAXN];
__device__ float  g_dis[MAXN];
__device__ int    g_offsets[MAXN + 1];
__device__ int    g_cursor[MAXN];
__device__ int    g_csr_src[MAXE];
__device__ float  g_csr_norm[MAXE];
__device__ float  g_h0[(size_t)MAXN * MAXF];
__device__ float  g_h1[(size_t)MAXN * MAXF];
__device__ __half g_Ahi[(size_t)MAXN * MAXF];
__device__ __half g_Alo[(size_t)MAXN * MAXF];
__device__ __half g_Chi[(size_t)MAXN * MAXF];
__device__ __half g_Clo[(size_t)MAXN * MAXF];
__device__ __half g_Bhi[(size_t)MAXF * MAXF];
__device__ __half g_Blo[(size_t)MAXF * MAXF];

__device__ __forceinline__ uint32_t smem_u32(const void* p) {
    uint32_t a;
    asm("{ .reg .u64 t; cvta.to.shared.u64 t, %1; cvt.u32.u64 %0, t; }" : "=r"(a) : "l"(p));
    return a;
}
__device__ __forceinline__ void ldsm_x4(uint32_t& r0, uint32_t& r1, uint32_t& r2, uint32_t& r3,
                                        uint32_t addr) {
    asm volatile("ldmatrix.sync.aligned.m8n8.x4.shared.b16 {%0,%1,%2,%3}, [%4];"
                 : "=r"(r0), "=r"(r1), "=r"(r2), "=r"(r3) : "r"(addr));
}
__device__ __forceinline__ void ldsm_x2(uint32_t& r0, uint32_t& r1, uint32_t addr) {
    asm volatile("ldmatrix.sync.aligned.m8n8.x2.shared.b16 {%0,%1}, [%2];"
                 : "=r"(r0), "=r"(r1) : "r"(addr));
}
__device__ __forceinline__ void mma16816(float* c, uint32_t a0, uint32_t a1, uint32_t a2,
                                         uint32_t a3, uint32_t b0, uint32_t b1) {
    asm volatile(
        "mma.sync.aligned.m16n8k16.row.col.f32.f16.f16.f32 "
        "{%0,%1,%2,%3}, {%4,%5,%6,%7}, {%8,%9}, {%0,%1,%2,%3};"
        : "+f"(c[0]), "+f"(c[1]), "+f"(c[2]), "+f"(c[3])
        : "r"(a0), "r"(a1), "r"(a2), "r"(a3), "r"(b0), "r"(b1));
}
__device__ __forceinline__ __half2 split_hi2(float a, float b, __half2& lo2) {
    __half ha = __float2half_rn(a), hb = __float2half_rn(b);
    lo2 = __halves2half2(__float2half_rn(a - __half2float(ha)),
                         __float2half_rn(b - __half2float(hb)));
    return __halves2half2(ha, hb);
}

// ---------------- preprocessing ----------------
__global__ void zero_indeg_kernel(int n) {
    int i = blockIdx.x * blockDim.x + threadIdx.x;
    if (i < n) g_indeg[i] = 0;
}
__global__ void count_indeg_kernel(const int* __restrict__ dst, int e) {
    int i = blockIdx.x * blockDim.x + threadIdx.x;
    if (i < e) atomicAdd(&g_indeg[dst[i]], 1);
}
__global__ void compute_dis_kernel(int n) {
    int i = blockIdx.x * blockDim.x + threadIdx.x;
    if (i < n) g_dis[i] = rsqrtf((float)(g_indeg[i] + 1));  // +1 self-loop
}

// spill-free two-pass scan: 1 block, 1024 threads
__global__ void scan_fast_kernel(int n) {
    const int tid = threadIdx.x;
    const int CH = (n + 1023) >> 10;
    const int base = tid * CH;
    int s = 0;
    for (int j = 0; j < CH; j++) {
        int i = base + j;
        if (i < n) s += g_indeg[i];
    }
    const int lane = tid & 31, w = tid >> 5;
    int inc = s;
    #pragma unroll
    for (int o = 1; o < 32; o <<= 1) { int t = __shfl_up_sync(~0u, inc, o); if (lane >= o) inc += t; }
    __shared__ int wsum[32];
    if (lane == 31) wsum[w] = inc;
    __syncthreads();
    if (w == 0) {
        int v = wsum[lane];
        int p = v;
        #pragma unroll
        for (int o = 1; o < 32; o <<= 1) { int t = __shfl_up_sync(~0u, p, o); if (lane >= o) p += t; }
        wsum[lane] = p - v;
    }
    __syncthreads();
    int run = wsum[w] + (inc - s);
    for (int j = 0; j < CH; j++) {
        int i = base + j;
        if (i < n) {
            int v = g_indeg[i];
            g_offsets[i] = run;
            g_cursor[i]  = run;
            run += v;
        }
    }
    if (tid == 1023) g_offsets[n] = run;
}

__global__ void fill_csr_kernel(const int* __restrict__ src, const int* __restrict__ dst, int e) {
    int i = blockIdx.x * blockDim.x + threadIdx.x;
    if (i < e) {
        int s = src[i], d = dst[i];
        int pos = atomicAdd(&g_cursor[d], 1);
        g_csr_src[pos]  = s;
        g_csr_norm[pos] = g_dis[s] * g_dis[d];
    }
}

// -------- W [K,N] row-major -> Bt [N,K] fp16 hi/lo split (tiled transpose) --------
__global__ void wsplit_t_kernel(const float* __restrict__ W, __half* __restrict__ hi,
                                __half* __restrict__ lo, int K, int N) {
    __shared__ float tile[32][33];
    const int bx = blockIdx.x * 32;   // N origin
    const int by = blockIdx.y * 32;   // K origin
    const int tx = threadIdx.x & 31, ty = threadIdx.x >> 5;
    #pragma unroll
    for (int r = 0; r < 32; r += 8)
        tile[ty + r][tx] = W[(size_t)(by + ty + r) * N + bx + tx];
    __syncthreads();
    #pragma unroll
    for (int r = 0; r < 32; r += 8) {
        float f = tile[tx][ty + r];   // = W[by+tx][bx+ty+r]
        __half h = __float2half_rn(f);
        size_t o = (size_t)(bx + ty + r) * K + by + tx;
        hi[o] = h;
        lo[o] = __float2half_rn(f - __half2float(h));
    }
}

// ============ HMMA fp16-split GEMM: C[M,N] = A[M,K] @ Bt[N,K]^T ============
// 128x128 block tile, BK=32, 256 threads (8 warps, 2m x 4n, 64x32 warp tiles).
// EPI=0: plain fp32 out.  EPI=1: bias+lrelu, split fp16 hi/lo out.
#define BM 128
#define BN 128
#define BK 32
#define APAD 8
#define ASTR (BK + APAD)   // 40 halves per row, conflict-free ldmatrix

template <int EPI>
__global__ void __launch_bounds__(256)
gemm_hmma_kernel(const __half* __restrict__ Ahi, const __half* __restrict__ Alo,
                 const __half* __restrict__ Bhi, const __half* __restrict__ Blo,
                 float* __restrict__ Cf, __half* __restrict__ Chi, __half* __restrict__ Clo,
                 const float* __restrict__ bias, int M, int N, int K) {
    __shared__ __half sAh[BM][ASTR];
    __shared__ __half sAl[BM][ASTR];
    __shared__ __half sBh[BN][ASTR];
    __shared__ __half sBl[BN][ASTR];

    const int tid = threadIdx.x;
    const int lane = tid & 31, wid = tid >> 5;
    const int wm = wid & 1;        // 0..1 (m)
    const int wn = wid >> 1;       // 0..3 (n)
    const int by = blockIdx.y;
    const int n0 = blockIdx.x * BN;

    float acc[4][4][4];
    #pragma unroll
    for (int mt = 0; mt < 4; mt++)
        #pragma unroll
        for (int nt = 0; nt < 4; nt++)
            #pragma unroll
            for (int r = 0; r < 4; r++) acc[mt][nt][r] = 0.f;

    const uint32_t aAh = smem_u32(&sAh[0][0]);
    const uint32_t aAl = smem_u32(&sAl[0][0]);
    const uint32_t aBh = smem_u32(&sBh[0][0]);
    const uint32_t aBl = smem_u32(&sBl[0][0]);
    const int a_msel = lane >> 3;
    const int a_rowin = (lane & 7) + ((a_msel & 1) << 3);
    const int a_colin = (a_msel >> 1) << 3;
    const int b_rowin = lane & 7;
    const int b_colin = ((lane >> 3) & 1) << 3;

    const int ldrow = tid >> 2;        // 0..63
    const int ldseg = (tid & 3) << 3;  // 0,8,16,24 halves

    for (int k0 = 0; k0 < K; k0 += BK) {
        #pragma unroll
        for (int h = 0; h < 2; h++) {
            const int row = ldrow + h * 64;
            const int ar = by * BM + row;
            uint4 vh = make_uint4(0, 0, 0, 0), vl = make_uint4(0, 0, 0, 0);
            if (ar < M) {
                size_t ai = (size_t)ar * K + k0 + ldseg;
                vh = *(const uint4*)(Ahi + ai);
                vl = *(const uint4*)(Alo + ai);
            }
            *(uint4*)(&sAh[row][ldseg]) = vh;
            *(uint4*)(&sAl[row][ldseg]) = vl;
            size_t bi = (size_t)(n0 + row) * K + k0 + ldseg;
            *(uint4*)(&sBh[row][ldseg]) = *(const uint4*)(Bhi + bi);
            *(uint4*)(&sBl[row][ldseg]) = *(const uint4*)(Blo + bi);
        }
        __syncthreads();

        #pragma unroll
        for (int ks = 0; ks < 2; ks++) {
            uint32_t bh[4][2], bl[4][2];
            #pragma unroll
            for (int nt = 0; nt < 4; nt++) {
                uint32_t boff = ((wn * 32 + nt * 8 + b_rowin) * ASTR + ks * 16 + b_colin) * 2;
                ldsm_x2(bh[nt][0], bh[nt][1], aBh + boff);
                ldsm_x2(bl[nt][0], bl[nt][1], aBl + boff);
            }
            #pragma unroll
            for (int mt = 0; mt < 4; mt++) {
                uint32_t aoff = ((wm * 64 + mt * 16 + a_rowin) * ASTR + ks * 16 + a_colin) * 2;
                uint32_t ah0, ah1, ah2, ah3, al0, al1, al2, al3;
                ldsm_x4(ah0, ah1, ah2, ah3, aAh + aoff);
                ldsm_x4(al0, al1, al2, al3, aAl + aoff);
                #pragma unroll
                for (int nt = 0; nt < 4; nt++) {
                    mma16816(acc[mt][nt], ah0, ah1, ah2, ah3, bh[nt][0], bh[nt][1]);
                    mma16816(acc[mt][nt], ah0, ah1, ah2, ah3, bl[nt][0], bl[nt][1]);
                    mma16816(acc[mt][nt], al0, al1, al2, al3, bh[nt][0], bh[nt][1]);
                }
            }
        }
        __syncthreads();
    }

    // ---- epilogue ----
    const int erow = lane >> 2;
    const int ecol = (lane & 3) << 1;
    #pragma unroll
    for (int mt = 0; mt < 4; mt++) {
        #pragma unroll
        for (int nt = 0; nt < 4; nt++) {
            const int gc = n0 + wn * 32 + nt * 8 + ecol;
            #pragma unroll
            for (int half = 0; half < 2; half++) {
                const int gr = by * BM + wm * 64 + mt * 16 + erow + half * 8;
                if (gr < M) {
                    float v0 = acc[mt][nt][half * 2 + 0];
                    float v1 = acc[mt][nt][half * 2 + 1];
                    if (EPI == 1) {
                        v0 += bias[gc];     v1 += bias[gc + 1];
                        v0 = (v0 > 0.f) ? v0 : 0.15f * v0;
                        v1 = (v1 > 0.f) ? v1 : 0.15f * v1;
                        __half2 lo2;
                        __half2 hi2 = split_hi2(v0, v1, lo2);
                        size_t o = (size_t)gr * N + gc;
                        *(__half2*)(Chi + o) = hi2;
                        *(__half2*)(Clo + o) = lo2;
                    } else {
                        *(float2*)(Cf + (size_t)gr * N + gc) = make_float2(v0, v1);
                    }
                }
            }
        }
    }
}

// ------- aggregation (warp per node, float4): out = [lrelu(]sum + self[+bias)] -------
template <int F, int OUT_SPLIT, int BIASACT>
__global__ void __launch_bounds__(256)
agg_warp_kernel(const float* __restrict__ h, float* __restrict__ outf,
                __half* __restrict__ ohi, __half* __restrict__ olo,
                const float* __restrict__ bias, int n) {
    const int gw = (blockIdx.x * blockDim.x + threadIdx.x) >> 5;
    const int lane = threadIdx.x & 31;
    if (gw >= n) return;
    constexpr int V = F / 128;

    float4 acc[V];
    const float di = g_dis[gw];
    const float selfw = di * di;
    const float4* hrow = (const float4*)(h + (size_t)gw * F);
    #pragma unroll
    for (int v = 0; v < V; v++) {
        float4 t = hrow[lane + 32 * v];
        acc[v] = make_float4(selfw * t.x, selfw * t.y, selfw * t.z, selfw * t.w);
    }

    const int beg = g_offsets[gw];
    const int end = g_offsets[gw + 1];
    for (int j = beg; j < end; j++) {
        const int   s = g_csr_src[j];
        const float w = g_csr_norm[j];
        const float4* hs = (const float4*)(h + (size_t)s * F);
        #pragma unroll
        for (int v = 0; v < V; v++) {
            float4 t = hs[lane + 32 * v];
            acc[v].x += w * t.x; acc[v].y += w * t.y;
            acc[v].z += w * t.z; acc[v].w += w * t.w;
        }
    }

    #pragma unroll
    for (int v = 0; v < V; v++) {
        float4 r = acc[v];
        if (BIASACT) {
            const float4 b = ((const float4*)bias)[lane + 32 * v];
            r.x += b.x; r.y += b.y; r.z += b.z; r.w += b.w;
            r.x = (r.x > 0.f) ? r.x : 0.15f * r.x;
            r.y = (r.y > 0.f) ? r.y : 0.15f * r.y;
            r.z = (r.z > 0.f) ? r.z : 0.15f * r.z;
            r.w = (r.w > 0.f) ? r.w : 0.15f * r.w;
        }
        const size_t o = (size_t)gw * F + (lane + 32 * v) * 4;
        if (OUT_SPLIT) {
            __half2 lo0, lo1;
            __half2 hi0 = split_hi2(r.x, r.y, lo0);
            __half2 hi1 = split_hi2(r.z, r.w, lo1);
            *(__half2*)(ohi + o)     = hi0;
            *(__half2*)(ohi + o + 2) = hi1;
            *(__half2*)(olo + o)     = lo0;
            *(__half2*)(olo + o + 2) = lo1;
        } else {
            *(float4*)(outf + o) = r;
        }
    }
}

// ---------------- fused head: h(128) -> 16 -> lrelu(32) -> 2 ----------------
__global__ __launch_bounds__(256)
void head_kernel(const float* __restrict__ h,
                 const float* __restrict__ Wp,  const float* __restrict__ bp,
                 const float* __restrict__ Wf1, const float* __restrict__ bf1,
                 const float* __restrict__ Wf2, const float* __restrict__ bf2,
                 float* __restrict__ out, int n) {
    __shared__ float sWp[128 * 16];
    __shared__ float sWf1[16 * 32];
    __shared__ float sWf2[32 * 2];
    __shared__ float sbp[16], sbf1[32], sbf2[2];

    for (int i = threadIdx.x; i < 128 * 16; i += 256) sWp[i] = Wp[i];
    for (int i = threadIdx.x; i < 16 * 32;  i += 256) sWf1[i] = Wf1[i];
    if (threadIdx.x < 64) sWf2[threadIdx.x] = Wf2[threadIdx.x];
    if (threadIdx.x < 16) sbp[threadIdx.x]  = bp[threadIdx.x];
    if (threadIdx.x < 32) sbf1[threadIdx.x] = bf1[threadIdx.x];
    if (threadIdx.x < 2)  sbf2[threadIdx.x] = bf2[threadIdx.x];
    __syncthreads();

    const int warp = threadIdx.x / 32, lane = threadIdx.x % 32;
    const int node = blockIdx.x * 8 + warp;
    if (node >= n) return;

    float hv[4];
    const float* hr = h + (size_t)node * 128;
    #pragma unroll
    for (int k = 0; k < 4; k++) hv[k] = hr[lane + 32 * k];

    float s16[16];
    #pragma unroll
    for (int j = 0; j < 16; j++) {
        float p = 0.f;
        #pragma unroll
        for (int k = 0; k < 4; k++) p += hv[k] * sWp[(lane + 32 * k) * 16 + j];
        #pragma unroll
        for (int o = 16; o > 0; o >>= 1) p += __shfl_xor_sync(0xffffffffu, p, o);
        s16[j] = p + sbp[j];
    }

    float tv = sbf1[lane];
    #pragma unroll
    for (int k = 0; k < 16; k++) tv += s16[k] * sWf1[k * 32 + lane];
    tv = (tv > 0.f) ? tv : 0.15f * tv;

    float v0 = tv * sWf2[lane * 2 + 0];
    float v1 = tv * sWf2[lane * 2 + 1];
    #pragma unroll
    for (int o = 16; o > 0; o >>= 1) {
        v0 += __shfl_xor_sync(0xffffffffu, v0, o);
        v1 += __shfl_xor_sync(0xffffffffu, v1, o);
    }
    if (lane == 0) {
        out[(size_t)node * 2 + 0] = v0 + sbf2[0];
        out[(size_t)node * 2 + 1] = v1 + sbf2[1];
    }
}

// ---------------- launch ----------------
extern "C" void kernel_launch(void* const* d_in, const int* in_sizes, int n_in,
                              void* d_out, int out_size) {
    const float* x   = (const float*)d_in[0];
    const int*   ei  = (const int*)  d_in[1];
    const float* W1  = (const float*)d_in[3];
    const float* b1  = (const float*)d_in[4];
    const float* W2  = (const float*)d_in[5];
    const float* b2  = (const float*)d_in[6];
    const float* W3  = (const float*)d_in[7];
    const float* b3  = (const float*)d_in[8];
    const float* Wp  = (const float*)d_in[9];
    const float* bp  = (const float*)d_in[10];
    const float* Wf1 = (const float*)d_in[11];
    const float* bf1 = (const float*)d_in[12];
    const float* Wf2 = (const float*)d_in[13];
    const float* bf2 = (const float*)d_in[14];
    float* out = (float*)d_out;

    const int N = in_sizes[0] / 128;
    const int E = in_sizes[1] / 2;
    const int* src = ei;
    const int* dst = ei + E;

    float *h0, *h1;
    __half *ahi, *alo, *chi, *clo, *bhi, *blo;
    cudaGetSymbolAddress((void**)&h0, g_h0);
    cudaGetSymbolAddress((void**)&h1, g_h1);
    cudaGetSymbolAddress((void**)&ahi, g_Ahi);
    cudaGetSymbolAddress((void**)&alo, g_Alo);
    cudaGetSymbolAddress((void**)&chi, g_Chi);
    cudaGetSymbolAddress((void**)&clo, g_Clo);
    cudaGetSymbolAddress((void**)&bhi, g_Bhi);
    cudaGetSymbolAddress((void**)&blo, g_Blo);

    __half *b1hi = bhi,          *b1lo = blo;            // 128*512
    __half *b2hi = bhi + 65536,  *b2lo = blo + 65536;    // 512*256
    __half *b3hi = bhi + 196608, *b3lo = blo + 196608;   // 256*128

    const int GM = (N + 127) / 128;
    const int AGG_BLK = (N * 32 + 255) / 256;

    // --- preprocessing first; agg1 at launch index 5 (ncu captures it) ---
    zero_indeg_kernel<<<(N + 255) / 256, 256>>>(N);                    // 0
    count_indeg_kernel<<<(E + 255) / 256, 256>>>(dst, E);              // 1
    compute_dis_kernel<<<(N + 255) / 256, 256>>>(N);                   // 2
    scan_fast_kernel<<<1, 1024>>>(N);                                  // 3
    fill_csr_kernel<<<(E + 255) / 256, 256>>>(src, dst, E);            // 4

    // --- layer 1 (aggregate-first): split(agg(x)) -> gemm(+bias+lrelu, split out) ---
    agg_warp_kernel<128, 1, 0><<<AGG_BLK, 256>>>(x, nullptr, ahi, alo, nullptr, N);  // 5
    { dim3 g(512 / 32, 128 / 32); wsplit_t_kernel<<<g, 256>>>(W1, b1hi, b1lo, 128, 512); }
    {
        dim3 grid(512 / 128, GM);
        gemm_hmma_kernel<1><<<grid, 256>>>(ahi, alo, b1hi, b1lo, nullptr,
                                           chi, clo, b1, N, 512, 128);
    }
    // --- layer 2 (transform-first): gemm -> agg(+bias+lrelu, split out) ---
    { dim3 g(256 / 32, 512 / 32); wsplit_t_kernel<<<g, 256>>>(W2, b2hi, b2lo, 512, 256); }
    {
        dim3 grid(256 / 128, GM);
        gemm_hmma_kernel<0><<<grid, 256>>>(chi, clo, b2hi, b2lo, h0, nullptr,
                                           nullptr, nullptr, N, 256, 512);
        agg_warp_kernel<256, 1, 1><<<AGG_BLK, 256>>>(h0, nullptr, ahi, alo, b2, N);
    }
    // --- layer 3: gemm -> agg(+bias+lrelu, fp32 out) -> head ---
    { dim3 g(128 / 32, 256 / 32); wsplit_t_kernel<<<g, 256>>>(W3, b3hi, b3lo, 256, 128); }
    {
        dim3 grid(128 / 128, GM);
        gemm_hmma_kernel<0><<<grid, 256>>>(ahi, alo, b3hi, b3lo, h0, nullptr,
                                           nullptr, nullptr, N, 128, 256);
        agg_warp_kernel<128, 0, 1><<<AGG_BLK, 256>>>(h0, h1, nullptr, nullptr, b3, N);
    }
    head_kernel<<<(N + 7) / 8, 256>>>(h1, Wp, bp, Wf1, bf1, Wf2, bf2, out, N);
}

// round 9
// speedup vs baseline: 1.6299x; 1.0646x over previous
#include <cuda_runtime.h>
#include <cuda_fp16.h>
#include <cuda_bf16.h>
#include <cstdint>

// Problem-fixed maxima: N=20000, E=320000, F up to 512
#define MAXN 20000
#define MAXE 320000
#define MAXF 512

// -------- scratch (static device memory; no allocations allowed) --------
__device__ int    g_indeg[MAXN];
__device__ float  g_dis[MAXN];
__device__ int    g_offsets[MAXN + 1];
__device__ int    g_cursor[MAXN];
__device__ int    g_part[128];
__device__ int    g_csr_src[MAXE];
__device__ float  g_csr_norm[MAXE];
__device__ float  g_h0[(size_t)MAXN * MAXF];
__device__ float  g_h1[(size_t)MAXN * MAXF];
__device__ __half g_Ahi[(size_t)MAXN * MAXF];
__device__ __half g_Alo[(size_t)MAXN * MAXF];
__device__ __half g_Chi[(size_t)MAXN * MAXF];
__device__ __half g_Clo[(size_t)MAXN * MAXF];
__device__ __half g_Bhi[(size_t)MAXF * MAXF];
__device__ __half g_Blo[(size_t)MAXF * MAXF];

__device__ __forceinline__ uint32_t smem_u32(const void* p) {
    uint32_t a;
    asm("{ .reg .u64 t; cvta.to.shared.u64 t, %1; cvt.u32.u64 %0, t; }" : "=r"(a) : "l"(p));
    return a;
}
__device__ __forceinline__ void ldsm_x4(uint32_t& r0, uint32_t& r1, uint32_t& r2, uint32_t& r3,
                                        uint32_t addr) {
    asm volatile("ldmatrix.sync.aligned.m8n8.x4.shared.b16 {%0,%1,%2,%3}, [%4];"
                 : "=r"(r0), "=r"(r1), "=r"(r2), "=r"(r3) : "r"(addr));
}
__device__ __forceinline__ void ldsm_x2(uint32_t& r0, uint32_t& r1, uint32_t addr) {
    asm volatile("ldmatrix.sync.aligned.m8n8.x2.shared.b16 {%0,%1}, [%2];"
                 : "=r"(r0), "=r"(r1) : "r"(addr));
}
__device__ __forceinline__ void mma16816(float* c, uint32_t a0, uint32_t a1, uint32_t a2,
                                         uint32_t a3, uint32_t b0, uint32_t b1) {
    asm volatile(
        "mma.sync.aligned.m16n8k16.row.col.f32.f16.f16.f32 "
        "{%0,%1,%2,%3}, {%4,%5,%6,%7}, {%8,%9}, {%0,%1,%2,%3};"
        : "+f"(c[0]), "+f"(c[1]), "+f"(c[2]), "+f"(c[3])
        : "r"(a0), "r"(a1), "r"(a2), "r"(a3), "r"(b0), "r"(b1));
}
__device__ __forceinline__ __half2 split_hi2(float a, float b, __half2& lo2) {
    __half ha = __float2half_rn(a), hb = __float2half_rn(b);
    lo2 = __halves2half2(__float2half_rn(a - __half2float(ha)),
                         __float2half_rn(b - __half2float(hb)));
    return __halves2half2(ha, hb);
}

// ---------------- preprocessing ----------------
__global__ void zero_indeg_kernel(int n) {
    int i = blockIdx.x * blockDim.x + threadIdx.x;
    if (i < n) g_indeg[i] = 0;
}
__global__ void count_indeg_kernel(const int* __restrict__ dst, int e) {
    int i = blockIdx.x * blockDim.x + threadIdx.x;
    if (i < e) atomicAdd(&g_indeg[dst[i]], 1);
}
__global__ void compute_dis_kernel(int n) {
    int i = blockIdx.x * blockDim.x + threadIdx.x;
    if (i < n) g_dis[i] = rsqrtf((float)(g_indeg[i] + 1));  // +1 self-loop
}

// ---- grid-wide 3-phase exclusive scan of g_indeg -> g_offsets/g_cursor ----
// phase 1: per-block (256 nodes) reduction into g_part
__global__ void scan_part_kernel(int n) {
    const int tid = threadIdx.x;
    const int i = blockIdx.x * 256 + tid;
    int v = (i < n) ? g_indeg[i] : 0;
    const int lane = tid & 31, w = tid >> 5;
    #pragma unroll
    for (int o = 16; o > 0; o >>= 1) v += __shfl_xor_sync(~0u, v, o);
    __shared__ int ws[8];
    if (lane == 0) ws[w] = v;
    __syncthreads();
    if (tid == 0) {
        int s = 0;
        #pragma unroll
        for (int k = 0; k < 8; k++) s += ws[k];
        g_part[blockIdx.x] = s;
    }
}
// phase 2: single small block scans the <=128 block sums (exclusive, in place)
__global__ void scan_bsum_kernel(int nb, int n) {
    const int tid = threadIdx.x;   // 128
    int v = (tid < nb) ? g_part[tid] : 0;
    const int lane = tid & 31, w = tid >> 5;
    int inc = v;
    #pragma unroll
    for (int o = 1; o < 32; o <<= 1) { int t = __shfl_up_sync(~0u, inc, o); if (lane >= o) inc += t; }
    __shared__ int ws[4];
    if (lane == 31) ws[w] = inc;
    __syncthreads();
    if (tid == 0) {
        int run = 0;
        #pragma unroll
        for (int k = 0; k < 4; k++) { int t = ws[k]; ws[k] = run; run += t; }
    }
    __syncthreads();
    int excl = ws[w] + inc - v;
    if (tid < nb) g_part[tid] = excl;
    if (tid == nb - 1) g_offsets[n] = excl + v;
}
// phase 3: per-block exclusive scan + base -> offsets/cursor
__global__ void scan_emit_kernel(int n) {
    const int tid = threadIdx.x;
    const int i = blockIdx.x * 256 + tid;
    int v = (i < n) ? g_indeg[i] : 0;
    const int lane = tid & 31, w = tid >> 5;
    int inc = v;
    #pragma unroll
    for (int o = 1; o < 32; o <<= 1) { int t = __shfl_up_sync(~0u, inc, o); if (lane >= o) inc += t; }
    __shared__ int ws[8];
    if (lane == 31) ws[w] = inc;
    __syncthreads();
    if (tid == 0) {
        int run = 0;
        #pragma unroll
        for (int k = 0; k < 8; k++) { int t = ws[k]; ws[k] = run; run += t; }
    }
    __syncthreads();
    if (i < n) {
        int off = g_part[blockIdx.x] + ws[w] + inc - v;
        g_offsets[i] = off;
        g_cursor[i]  = off;
    }
}

__global__ void fill_csr_kernel(const int* __restrict__ src, const int* __restrict__ dst, int e) {
    int i = blockIdx.x * blockDim.x + threadIdx.x;
    if (i < e) {
        int s = src[i], d = dst[i];
        int pos = atomicAdd(&g_cursor[d], 1);
        g_csr_src[pos]  = s;
        g_csr_norm[pos] = g_dis[s] * g_dis[d];
    }
}

// -------- W [K,N] row-major -> Bt [N,K] fp16 hi/lo split (tiled transpose) --------
__global__ void wsplit_t_kernel(const float* __restrict__ W, __half* __restrict__ hi,
                                __half* __restrict__ lo, int K, int N) {
    __shared__ float tile[32][33];
    const int bx = blockIdx.x * 32;   // N origin
    const int by = blockIdx.y * 32;   // K origin
    const int tx = threadIdx.x & 31, ty = threadIdx.x >> 5;
    #pragma unroll
    for (int r = 0; r < 32; r += 8)
        tile[ty + r][tx] = W[(size_t)(by + ty + r) * N + bx + tx];
    __syncthreads();
    #pragma unroll
    for (int r = 0; r < 32; r += 8) {
        float f = tile[tx][ty + r];   // = W[by+tx][bx+ty+r]
        __half h = __float2half_rn(f);
        size_t o = (size_t)(bx + ty + r) * K + by + tx;
        hi[o] = h;
        lo[o] = __float2half_rn(f - __half2float(h));
    }
}

// ============ HMMA fp16-split GEMM: C[M,N] = A[M,K] @ Bt[N,K]^T ============
// 128x128 block tile, BK=32, 256 threads (8 warps, 2m x 4n, 64x32 warp tiles).
// EPI=0: plain fp32 out.  EPI=1: bias+lrelu, split fp16 hi/lo out.
#define BM 128
#define BN 128
#define BK 32
#define APAD 8
#define ASTR (BK + APAD)   // 40 halves per row, conflict-free ldmatrix

template <int EPI>
__global__ void __launch_bounds__(256)
gemm_hmma_kernel(const __half* __restrict__ Ahi, const __half* __restrict__ Alo,
                 const __half* __restrict__ Bhi, const __half* __restrict__ Blo,
                 float* __restrict__ Cf, __half* __restrict__ Chi, __half* __restrict__ Clo,
                 const float* __restrict__ bias, int M, int N, int K) {
    __shared__ __half sAh[BM][ASTR];
    __shared__ __half sAl[BM][ASTR];
    __shared__ __half sBh[BN][ASTR];
    __shared__ __half sBl[BN][ASTR];

    const int tid = threadIdx.x;
    const int lane = tid & 31, wid = tid >> 5;
    const int wm = wid & 1;        // 0..1 (m)
    const int wn = wid >> 1;       // 0..3 (n)
    const int by = blockIdx.y;
    const int n0 = blockIdx.x * BN;

    float acc[4][4][4];
    #pragma unroll
    for (int mt = 0; mt < 4; mt++)
        #pragma unroll
        for (int nt = 0; nt < 4; nt++)
            #pragma unroll
            for (int r = 0; r < 4; r++) acc[mt][nt][r] = 0.f;

    const uint32_t aAh = smem_u32(&sAh[0][0]);
    const uint32_t aAl = smem_u32(&sAl[0][0]);
    const uint32_t aBh = smem_u32(&sBh[0][0]);
    const uint32_t aBl = smem_u32(&sBl[0][0]);
    const int a_msel = lane >> 3;
    const int a_rowin = (lane & 7) + ((a_msel & 1) << 3);
    const int a_colin = (a_msel >> 1) << 3;
    const int b_rowin = lane & 7;
    const int b_colin = ((lane >> 3) & 1) << 3;

    const int ldrow = tid >> 2;        // 0..63
    const int ldseg = (tid & 3) << 3;  // 0,8,16,24 halves

    for (int k0 = 0; k0 < K; k0 += BK) {
        #pragma unroll
        for (int h = 0; h < 2; h++) {
            const int row = ldrow + h * 64;
            const int ar = by * BM + row;
            uint4 vh = make_uint4(0, 0, 0, 0), vl = make_uint4(0, 0, 0, 0);
            if (ar < M) {
                size_t ai = (size_t)ar * K + k0 + ldseg;
                vh = *(const uint4*)(Ahi + ai);
                vl = *(const uint4*)(Alo + ai);
            }
            *(uint4*)(&sAh[row][ldseg]) = vh;
            *(uint4*)(&sAl[row][ldseg]) = vl;
            size_t bi = (size_t)(n0 + row) * K + k0 + ldseg;
            *(uint4*)(&sBh[row][ldseg]) = *(const uint4*)(Bhi + bi);
            *(uint4*)(&sBl[row][ldseg]) = *(const uint4*)(Blo + bi);
        }
        __syncthreads();

        #pragma unroll
        for (int ks = 0; ks < 2; ks++) {
            uint32_t bh[4][2], bl[4][2];
            #pragma unroll
            for (int nt = 0; nt < 4; nt++) {
                uint32_t boff = ((wn * 32 + nt * 8 + b_rowin) * ASTR + ks * 16 + b_colin) * 2;
                ldsm_x2(bh[nt][0], bh[nt][1], aBh + boff);
                ldsm_x2(bl[nt][0], bl[nt][1], aBl + boff);
            }
            #pragma unroll
            for (int mt = 0; mt < 4; mt++) {
                uint32_t aoff = ((wm * 64 + mt * 16 + a_rowin) * ASTR + ks * 16 + a_colin) * 2;
                uint32_t ah0, ah1, ah2, ah3, al0, al1, al2, al3;
                ldsm_x4(ah0, ah1, ah2, ah3, aAh + aoff);
                ldsm_x4(al0, al1, al2, al3, aAl + aoff);
                #pragma unroll
                for (int nt = 0; nt < 4; nt++) {
                    mma16816(acc[mt][nt], ah0, ah1, ah2, ah3, bh[nt][0], bh[nt][1]);
                    mma16816(acc[mt][nt], ah0, ah1, ah2, ah3, bl[nt][0], bl[nt][1]);
                    mma16816(acc[mt][nt], al0, al1, al2, al3, bh[nt][0], bh[nt][1]);
                }
            }
        }
        __syncthreads();
    }

    // ---- epilogue ----
    const int erow = lane >> 2;
    const int ecol = (lane & 3) << 1;
    #pragma unroll
    for (int mt = 0; mt < 4; mt++) {
        #pragma unroll
        for (int nt = 0; nt < 4; nt++) {
            const int gc = n0 + wn * 32 + nt * 8 + ecol;
            #pragma unroll
            for (int half = 0; half < 2; half++) {
                const int gr = by * BM + wm * 64 + mt * 16 + erow + half * 8;
                if (gr < M) {
                    float v0 = acc[mt][nt][half * 2 + 0];
                    float v1 = acc[mt][nt][half * 2 + 1];
                    if (EPI == 1) {
                        v0 += bias[gc];     v1 += bias[gc + 1];
                        v0 = (v0 > 0.f) ? v0 : 0.15f * v0;
                        v1 = (v1 > 0.f) ? v1 : 0.15f * v1;
                        __half2 lo2;
                        __half2 hi2 = split_hi2(v0, v1, lo2);
                        size_t o = (size_t)gr * N + gc;
                        *(__half2*)(Chi + o) = hi2;
                        *(__half2*)(Clo + o) = lo2;
                    } else {
                        *(float2*)(Cf + (size_t)gr * N + gc) = make_float2(v0, v1);
                    }
                }
            }
        }
    }
}

// ------- aggregation (warp per node, float4): out = [lrelu(]sum + self[+bias)] -------
template <int F, int OUT_SPLIT, int BIASACT>
__global__ void __launch_bounds__(256)
agg_warp_kernel(const float* __restrict__ h, float* __restrict__ outf,
                __half* __restrict__ ohi, __half* __restrict__ olo,
                const float* __restrict__ bias, int n) {
    const int gw = (blockIdx.x * blockDim.x + threadIdx.x) >> 5;
    const int lane = threadIdx.x & 31;
    if (gw >= n) return;
    constexpr int V = F / 128;

    float4 acc[V];
    const float di = g_dis[gw];
    const float selfw = di * di;
    const float4* hrow = (const float4*)(h + (size_t)gw * F);
    #pragma unroll
    for (int v = 0; v < V; v++) {
        float4 t = hrow[lane + 32 * v];
        acc[v] = make_float4(selfw * t.x, selfw * t.y, selfw * t.z, selfw * t.w);
    }

    const int beg = g_offsets[gw];
    const int end = g_offsets[gw + 1];
    for (int j = beg; j < end; j++) {
        const int   s = g_csr_src[j];
        const float w = g_csr_norm[j];
        const float4* hs = (const float4*)(h + (size_t)s * F);
        #pragma unroll
        for (int v = 0; v < V; v++) {
            float4 t = hs[lane + 32 * v];
            acc[v].x += w * t.x; acc[v].y += w * t.y;
            acc[v].z += w * t.z; acc[v].w += w * t.w;
        }
    }

    #pragma unroll
    for (int v = 0; v < V; v++) {
        float4 r = acc[v];
        if (BIASACT) {
            const float4 b = ((const float4*)bias)[lane + 32 * v];
            r.x += b.x; r.y += b.y; r.z += b.z; r.w += b.w;
            r.x = (r.x > 0.f) ? r.x : 0.15f * r.x;
            r.y = (r.y > 0.f) ? r.y : 0.15f * r.y;
            r.z = (r.z > 0.f) ? r.z : 0.15f * r.z;
            r.w = (r.w > 0.f) ? r.w : 0.15f * r.w;
        }
        const size_t o = (size_t)gw * F + (lane + 32 * v) * 4;
        if (OUT_SPLIT) {
            __half2 lo0, lo1;
            __half2 hi0 = split_hi2(r.x, r.y, lo0);
            __half2 hi1 = split_hi2(r.z, r.w, lo1);
            *(__half2*)(ohi + o)     = hi0;
            *(__half2*)(ohi + o + 2) = hi1;
            *(__half2*)(olo + o)     = lo0;
            *(__half2*)(olo + o + 2) = lo1;
        } else {
            *(float4*)(outf + o) = r;
        }
    }
}

// ---------------- fused head: h(128) -> 16 -> lrelu(32) -> 2 ----------------
__global__ __launch_bounds__(256)
void head_kernel(const float* __restrict__ h,
                 const float* __restrict__ Wp,  const float* __restrict__ bp,
                 const float* __restrict__ Wf1, const float* __restrict__ bf1,
                 const float* __restrict__ Wf2, const float* __restrict__ bf2,
                 float* __restrict__ out, int n) {
    __shared__ float sWp[128 * 16];
    __shared__ float sWf1[16 * 32];
    __shared__ float sWf2[32 * 2];
    __shared__ float sbp[16], sbf1[32], sbf2[2];

    for (int i = threadIdx.x; i < 128 * 16; i += 256) sWp[i] = Wp[i];
    for (int i = threadIdx.x; i < 16 * 32;  i += 256) sWf1[i] = Wf1[i];
    if (threadIdx.x < 64) sWf2[threadIdx.x] = Wf2[threadIdx.x];
    if (threadIdx.x < 16) sbp[threadIdx.x]  = bp[threadIdx.x];
    if (threadIdx.x < 32) sbf1[threadIdx.x] = bf1[threadIdx.x];
    if (threadIdx.x < 2)  sbf2[threadIdx.x] = bf2[threadIdx.x];
    __syncthreads();

    const int warp = threadIdx.x / 32, lane = threadIdx.x % 32;
    const int node = blockIdx.x * 8 + warp;
    if (node >= n) return;

    float hv[4];
    const float* hr = h + (size_t)node * 128;
    #pragma unroll
    for (int k = 0; k < 4; k++) hv[k] = hr[lane + 32 * k];

    float s16[16];
    #pragma unroll
    for (int j = 0; j < 16; j++) {
        float p = 0.f;
        #pragma unroll
        for (int k = 0; k < 4; k++) p += hv[k] * sWp[(lane + 32 * k) * 16 + j];
        #pragma unroll
        for (int o = 16; o > 0; o >>= 1) p += __shfl_xor_sync(0xffffffffu, p, o);
        s16[j] = p + sbp[j];
    }

    float tv = sbf1[lane];
    #pragma unroll
    for (int k = 0; k < 16; k++) tv += s16[k] * sWf1[k * 32 + lane];
    tv = (tv > 0.f) ? tv : 0.15f * tv;

    float v0 = tv * sWf2[lane * 2 + 0];
    float v1 = tv * sWf2[lane * 2 + 1];
    #pragma unroll
    for (int o = 16; o > 0; o >>= 1) {
        v0 += __shfl_xor_sync(0xffffffffu, v0, o);
        v1 += __shfl_xor_sync(0xffffffffu, v1, o);
    }
    if (lane == 0) {
        out[(size_t)node * 2 + 0] = v0 + sbf2[0];
        out[(size_t)node * 2 + 1] = v1 + sbf2[1];
    }
}

// ---------------- launch ----------------
extern "C" void kernel_launch(void* const* d_in, const int* in_sizes, int n_in,
                              void* d_out, int out_size) {
    const float* x   = (const float*)d_in[0];
    const int*   ei  = (const int*)  d_in[1];
    const float* W1  = (const float*)d_in[3];
    const float* b1  = (const float*)d_in[4];
    const float* W2  = (const float*)d_in[5];
    const float* b2  = (const float*)d_in[6];
    const float* W3  = (const float*)d_in[7];
    const float* b3  = (const float*)d_in[8];
    const float* Wp  = (const float*)d_in[9];
    const float* bp  = (const float*)d_in[10];
    const float* Wf1 = (const float*)d_in[11];
    const float* bf1 = (const float*)d_in[12];
    const float* Wf2 = (const float*)d_in[13];
    const float* bf2 = (const float*)d_in[14];
    float* out = (float*)d_out;

    const int N = in_sizes[0] / 128;
    const int E = in_sizes[1] / 2;
    const int* src = ei;
    const int* dst = ei + E;

    float *h0, *h1;
    __half *ahi, *alo, *chi, *clo, *bhi, *blo;
    cudaGetSymbolAddress((void**)&h0, g_h0);
    cudaGetSymbolAddress((void**)&h1, g_h1);
    cudaGetSymbolAddress((void**)&ahi, g_Ahi);
    cudaGetSymbolAddress((void**)&alo, g_Alo);
    cudaGetSymbolAddress((void**)&chi, g_Chi);
    cudaGetSymbolAddress((void**)&clo, g_Clo);
    cudaGetSymbolAddress((void**)&bhi, g_Bhi);
    cudaGetSymbolAddress((void**)&blo, g_Blo);

    __half *b1hi = bhi,          *b1lo = blo;            // 128*512
    __half *b2hi = bhi + 65536,  *b2lo = blo + 65536;    // 512*256
    __half *b3hi = bhi + 196608, *b3lo = blo + 196608;   // 256*128

    const int GM = (N + 127) / 128;
    const int AGG_BLK = (N * 32 + 255) / 256;
    const int NB = (N + 255) / 256;   // scan blocks (<=128)

    // --- preprocessing ---
    zero_indeg_kernel<<<(N + 255) / 256, 256>>>(N);
    count_indeg_kernel<<<(E + 255) / 256, 256>>>(dst, E);
    compute_dis_kernel<<<(N + 255) / 256, 256>>>(N);
    scan_part_kernel<<<NB, 256>>>(N);
    scan_bsum_kernel<<<1, 128>>>(NB, N);
    scan_emit_kernel<<<NB, 256>>>(N);
    fill_csr_kernel<<<(E + 255) / 256, 256>>>(src, dst, E);

    // --- layer 1 (aggregate-first): split(agg(x)) -> gemm(+bias+lrelu, split out) ---
    agg_warp_kernel<128, 1, 0><<<AGG_BLK, 256>>>(x, nullptr, ahi, alo, nullptr, N);
    { dim3 g(512 / 32, 128 / 32); wsplit_t_kernel<<<g, 256>>>(W1, b1hi, b1lo, 128, 512); }
    {
        dim3 grid(512 / 128, GM);
        gemm_hmma_kernel<1><<<grid, 256>>>(ahi, alo, b1hi, b1lo, nullptr,
                                           chi, clo, b1, N, 512, 128);
    }
    // --- layer 2 (transform-first): gemm -> agg(+bias+lrelu, split out) ---
    { dim3 g(256 / 32, 512 / 32); wsplit_t_kernel<<<g, 256>>>(W2, b2hi, b2lo, 512, 256); }
    {
        dim3 grid(256 / 128, GM);
        gemm_hmma_kernel<0><<<grid, 256>>>(chi, clo, b2hi, b2lo, h0, nullptr,
                                           nullptr, nullptr, N, 256, 512);
        agg_warp_kernel<256, 1, 1><<<AGG_BLK, 256>>>(h0, nullptr, ahi, alo, b2, N);
    }
    // --- layer 3: gemm -> agg(+bias+lrelu, fp32 out) -> head ---
    { dim3 g(128 / 32, 256 / 32); wsplit_t_kernel<<<g, 256>>>(W3, b3hi, b3lo, 256, 128); }
    {
        dim3 grid(128 / 128, GM);
        gemm_hmma_kernel<0><<<grid, 256>>>(ahi, alo, b3hi, b3lo, h0, nullptr,
                                           nullptr, nullptr, N, 128, 256);
        agg_warp_kernel<128, 0, 1><<<AGG_BLK, 256>>>(h0, h1, nullptr, nullptr, b3, N);
    }
    head_kernel<<<(N + 7) / 8, 256>>>(h1, Wp, bp, Wf1, bf1, Wf2, bf2, out, N);
}